// round 4
// baseline (speedup 1.0000x reference)
#include <cuda_runtime.h>

#define N_NODES 50000
#define N_EDGES 640000
#define FDIM    128
#define OUT_DIM 16
#define BATCH   2
#define M_ROWS  (BATCH * N_NODES)   /* 100000 flattened rows */
#define EPSBN   1e-5f
#define NBLK_SCAN ((N_NODES + 255) / 256)   /* 196 */
#define N_EDGES_PAD (N_EDGES + 7 * N_NODES) /* 990000: every count padded to mult of 8 */

// ---------------- scratch (device globals; no allocation allowed) -------------
__device__ __align__(128) float g_xw  [(size_t)M_ROWS * FDIM];  // GEMM outputs
__device__ __align__(128) float g_t   [(size_t)M_ROWS * FDIM];  // relu(conv) activations
__device__ __align__(128) float g_dinv[N_NODES];
__device__ __align__(128) float g_deg [N_NODES];
__device__ __align__(128) int   g_cnt   [N_NODES];
__device__ __align__(128) int   g_start [N_NODES + 1];
__device__ __align__(128) int   g_cursor[N_NODES];
__device__ __align__(128) int   g_partial[256];
__device__ __align__(128) int   g_pscan  [256];
__device__ __align__(128) uint2 g_edge  [N_EDGES_PAD];          // {src, norm-bits} sorted by dst, padded
__device__ __align__(128) float g_W2p [FDIM * FDIM];
__device__ __align__(128) float g_cvec[FDIM];
__device__ __align__(128) float g_Wcp [FDIM * OUT_DIM];
__device__ __align__(128) float g_bcp [OUT_DIM];
__device__ __align__(128) float g_sum [FDIM];
__device__ __align__(128) float g_sq  [FDIM];

// ---------------- init: deg=1 (self loop), cnt=0 ----------------------------
__global__ void k_init(float* deg, int* cnt) {
    int i = blockIdx.x * blockDim.x + threadIdx.x;
    if (i < N_NODES) { deg[i] = 1.0f; cnt[i] = 0; }
}

// ---------------- pass1: degree accumulation + dst histogram -----------------
__global__ void k_pass1(const float* __restrict__ ewp, const int* __restrict__ col,
                        float* deg, int* cnt) {
    int e = blockIdx.x * blockDim.x + threadIdx.x;
    if (e < N_EDGES) {
        int c = col[e];
        atomicAdd(&deg[c], expf(ewp[e]));
        atomicAdd(&cnt[c], 1);
    }
}

__global__ void k_dinv(const float* __restrict__ deg, float* dinv) {
    int i = blockIdx.x * blockDim.x + threadIdx.x;
    if (i < N_NODES) {
        float d = deg[i];
        dinv[i] = (d > 0.f) ? rsqrtf(d) : 0.f;
    }
}

// ---------------- hierarchical scan over PADDED counts -----------------------
__global__ void k_scan1(const int* __restrict__ cnt, int* __restrict__ partial) {
    __shared__ int sh[8];
    int idx = blockIdx.x * 256 + threadIdx.x;
    int v = (idx < N_NODES) ? ((cnt[idx] + 7) & ~7) : 0;
    #pragma unroll
    for (int off = 16; off; off >>= 1) v += __shfl_down_sync(0xffffffffu, v, off);
    if ((threadIdx.x & 31) == 0) sh[threadIdx.x >> 5] = v;
    __syncthreads();
    if (threadIdx.x == 0) {
        int s = 0;
        #pragma unroll
        for (int w = 0; w < 8; w++) s += sh[w];
        partial[blockIdx.x] = s;
    }
}

__global__ void k_scan2(const int* __restrict__ partial, int* __restrict__ pscan,
                        int* __restrict__ start) {
    __shared__ int sh[256];
    int t = threadIdx.x;
    int v = (t < NBLK_SCAN) ? partial[t] : 0;
    sh[t] = v;
    __syncthreads();
    #pragma unroll
    for (int off = 1; off < 256; off <<= 1) {
        int u = (t >= off) ? sh[t - off] : 0;
        __syncthreads();
        sh[t] += u;
        __syncthreads();
    }
    if (t < NBLK_SCAN) pscan[t] = sh[t] - v;   // exclusive
    if (t == 255) start[N_NODES] = sh[255];    // total padded edge count
}

__global__ void k_scan3(const int* __restrict__ cnt, const int* __restrict__ pscan,
                        int* __restrict__ start, int* __restrict__ cursor) {
    __shared__ int sh[256];
    int t = threadIdx.x;
    int idx = blockIdx.x * 256 + t;
    int v = (idx < N_NODES) ? ((cnt[idx] + 7) & ~7) : 0;
    sh[t] = v;
    __syncthreads();
    #pragma unroll
    for (int off = 1; off < 256; off <<= 1) {
        int u = (t >= off) ? sh[t - off] : 0;
        __syncthreads();
        sh[t] += u;
        __syncthreads();
    }
    if (idx < N_NODES) {
        int excl = sh[t] - v + pscan[blockIdx.x];
        start[idx] = excl;
        cursor[idx] = excl;
    }
}

// ---------------- pad fill: zero-weight edges at node 0 ----------------------
__global__ void k_padfill(const int* __restrict__ cnt, const int* __restrict__ start,
                          uint2* __restrict__ edge) {
    int n = blockIdx.x * blockDim.x + threadIdx.x;
    if (n < N_NODES) {
        int b = start[n] + cnt[n];
        int e = start[n + 1];
        for (int i = b; i < e; i++) edge[i] = make_uint2(0u, 0u);
    }
}

// ---------------- bucket scatter: sorted {src, norm} per destination ---------
__global__ void k_sortedges(const float* __restrict__ ewp, const int* __restrict__ row,
                            const int* __restrict__ col, const float* __restrict__ dinv,
                            int* cursor, uint2* __restrict__ edge) {
    int e = blockIdx.x * blockDim.x + threadIdx.x;
    if (e < N_EDGES) {
        int r = row[e];
        int c = col[e];
        float nm = dinv[r] * expf(ewp[e]) * dinv[c];
        int pos = atomicAdd(&cursor[c], 1);
        edge[pos] = make_uint2((unsigned)r, __float_as_uint(nm));
    }
}

// ---------------- GEMM: C[M x128] = A[M x128] @ W[128x128] (+ cvec) ----------
__global__ __launch_bounds__(256) void k_gemm128(const float* __restrict__ A,
                                                 const float* __restrict__ W,
                                                 const float* __restrict__ cvec,
                                                 float* __restrict__ C, int Mrows) {
    extern __shared__ float smem[];
    float* sW = smem;            // 128*128 floats = 64 KB
    float* sA = smem + 16384;    // 64*128 floats = 32 KB
    const int tid = threadIdx.x;

    {   // load W once per block
        const float4* W4 = (const float4*)W;
        float4* sW4 = (float4*)sW;
        #pragma unroll
        for (int i = 0; i < 16; i++) sW4[tid + i * 256] = W4[tid + i * 256];
    }

    const int tc = tid & 15;   // cols 8*tc .. 8*tc+7
    const int tr = tid >> 4;   // rows 4*tr .. 4*tr+3

    unsigned long long initc[4];
    if (cvec) {
        #pragma unroll
        for (int p = 0; p < 4; p++) {
            float2 cv2 = *(const float2*)(cvec + 8 * tc + 2 * p);
            asm("mov.b64 %0, {%1, %2};" : "=l"(initc[p]) : "f"(cv2.x), "f"(cv2.y));
        }
    } else {
        #pragma unroll
        for (int p = 0; p < 4; p++) initc[p] = 0ull;
    }

    const int ntiles = (Mrows + 63) >> 6;
    for (int tile = blockIdx.x; tile < ntiles; tile += gridDim.x) {
        const int base = tile << 6;
        __syncthreads();
        #pragma unroll
        for (int i = 0; i < 8; i++) {
            int f4 = tid + i * 256;
            int r = f4 >> 5;
            int c4 = f4 & 31;
            int grow = base + r;
            float4 v = make_float4(0.f, 0.f, 0.f, 0.f);
            if (grow < Mrows) v = ((const float4*)A)[(size_t)grow * 32 + c4];
            ((float4*)sA)[f4] = v;
        }
        __syncthreads();

        unsigned long long acc[4][4];
        #pragma unroll
        for (int r = 0; r < 4; r++)
            #pragma unroll
            for (int p = 0; p < 4; p++) acc[r][p] = initc[p];

        const float* aBase = sA + (tr << 2) * FDIM;
        #pragma unroll 2
        for (int k0 = 0; k0 < FDIM; k0 += 4) {
            float4 a0 = *(const float4*)(aBase + k0);
            float4 a1 = *(const float4*)(aBase + FDIM + k0);
            float4 a2 = *(const float4*)(aBase + 2 * FDIM + k0);
            float4 a3 = *(const float4*)(aBase + 3 * FDIM + k0);
            float am[4][4] = {{a0.x, a0.y, a0.z, a0.w}, {a1.x, a1.y, a1.z, a1.w},
                              {a2.x, a2.y, a2.z, a2.w}, {a3.x, a3.y, a3.z, a3.w}};
            #pragma unroll
            for (int kk = 0; kk < 4; kk++) {
                const ulonglong2* bp = (const ulonglong2*)(sW + (k0 + kk) * FDIM + (tc << 3));
                ulonglong2 b01 = bp[0];
                ulonglong2 b23 = bp[1];
                unsigned long long bv[4] = {b01.x, b01.y, b23.x, b23.y};
                unsigned long long pa[4];
                #pragma unroll
                for (int r = 0; r < 4; r++)
                    asm("mov.b64 %0, {%1, %1};" : "=l"(pa[r]) : "f"(am[r][kk]));
                #pragma unroll
                for (int r = 0; r < 4; r++)
                    #pragma unroll
                    for (int p = 0; p < 4; p++)
                        asm("fma.rn.f32x2 %0, %1, %2, %0;"
                            : "+l"(acc[r][p]) : "l"(pa[r]), "l"(bv[p]));
            }
        }

        #pragma unroll
        for (int r = 0; r < 4; r++) {
            int grow = base + (tr << 2) + r;
            if (grow < Mrows) {
                ulonglong2* cp = (ulonglong2*)(C + (size_t)grow * FDIM + (tc << 3));
                cp[0] = make_ulonglong2(acc[r][0], acc[r][1]);
                cp[1] = make_ulonglong2(acc[r][2], acc[r][3]);
            }
        }
    }
}

// ---------------- fused aggregate + self-loop + bias + relu + BN stats -------
// ONE batch per launch; warp per node; edge lists padded to multiples of 8 ->
// branch-free 8-deep unrolled body, uint4 metadata loads, 8 gathers in flight.
__global__ __launch_bounds__(256) void k_agg(const float* __restrict__ xwb,
                                             const uint2* __restrict__ edge,
                                             const int* __restrict__ start,
                                             const float* __restrict__ dinv,
                                             const float* __restrict__ bias,
                                             float* __restrict__ tb,
                                             float* __restrict__ gsum,
                                             float* __restrict__ gsq) {
    const int tid = threadIdx.x;
    const int lane = tid & 31;
    const int gw = (blockIdx.x * blockDim.x + tid) >> 5;
    const int nwarps = (gridDim.x * blockDim.x) >> 5;
    const float4 bv = ((const float4*)bias)[lane];
    float s[4] = {0.f, 0.f, 0.f, 0.f}, q[4] = {0.f, 0.f, 0.f, 0.f};

    for (int n = gw; n < N_NODES; n += nwarps) {
        const int st = start[n];
        const int en = start[n + 1];
        const float d = dinv[n];
        const float d2 = d * d;
        float4 v = __ldg((const float4*)(xwb + (size_t)n * FDIM) + lane);
        float4 acc = make_float4(d2 * v.x, d2 * v.y, d2 * v.z, d2 * v.w);

        for (int e = st; e < en; e += 8) {
            // 8 edges of metadata as 4 aligned uint4 loads (start is mult of 8)
            const uint4* mp = (const uint4*)(edge + e);
            uint4 u0 = __ldg(mp);
            uint4 u1 = __ldg(mp + 1);
            uint4 u2 = __ldg(mp + 2);
            uint4 u3 = __ldg(mp + 3);
            // 8 independent row gathers
            float4 a0 = __ldg((const float4*)(xwb + (size_t)u0.x * FDIM) + lane);
            float4 a1 = __ldg((const float4*)(xwb + (size_t)u0.z * FDIM) + lane);
            float4 a2 = __ldg((const float4*)(xwb + (size_t)u1.x * FDIM) + lane);
            float4 a3 = __ldg((const float4*)(xwb + (size_t)u1.z * FDIM) + lane);
            float4 a4 = __ldg((const float4*)(xwb + (size_t)u2.x * FDIM) + lane);
            float4 a5 = __ldg((const float4*)(xwb + (size_t)u2.z * FDIM) + lane);
            float4 a6 = __ldg((const float4*)(xwb + (size_t)u3.x * FDIM) + lane);
            float4 a7 = __ldg((const float4*)(xwb + (size_t)u3.z * FDIM) + lane);
            float w0 = __uint_as_float(u0.y), w1 = __uint_as_float(u0.w);
            float w2 = __uint_as_float(u1.y), w3 = __uint_as_float(u1.w);
            float w4 = __uint_as_float(u2.y), w5 = __uint_as_float(u2.w);
            float w6 = __uint_as_float(u3.y), w7 = __uint_as_float(u3.w);
            acc.x = fmaf(w0, a0.x, acc.x); acc.y = fmaf(w0, a0.y, acc.y);
            acc.z = fmaf(w0, a0.z, acc.z); acc.w = fmaf(w0, a0.w, acc.w);
            acc.x = fmaf(w1, a1.x, acc.x); acc.y = fmaf(w1, a1.y, acc.y);
            acc.z = fmaf(w1, a1.z, acc.z); acc.w = fmaf(w1, a1.w, acc.w);
            acc.x = fmaf(w2, a2.x, acc.x); acc.y = fmaf(w2, a2.y, acc.y);
            acc.z = fmaf(w2, a2.z, acc.z); acc.w = fmaf(w2, a2.w, acc.w);
            acc.x = fmaf(w3, a3.x, acc.x); acc.y = fmaf(w3, a3.y, acc.y);
            acc.z = fmaf(w3, a3.z, acc.z); acc.w = fmaf(w3, a3.w, acc.w);
            acc.x = fmaf(w4, a4.x, acc.x); acc.y = fmaf(w4, a4.y, acc.y);
            acc.z = fmaf(w4, a4.z, acc.z); acc.w = fmaf(w4, a4.w, acc.w);
            acc.x = fmaf(w5, a5.x, acc.x); acc.y = fmaf(w5, a5.y, acc.y);
            acc.z = fmaf(w5, a5.z, acc.z); acc.w = fmaf(w5, a5.w, acc.w);
            acc.x = fmaf(w6, a6.x, acc.x); acc.y = fmaf(w6, a6.y, acc.y);
            acc.z = fmaf(w6, a6.z, acc.z); acc.w = fmaf(w6, a6.w, acc.w);
            acc.x = fmaf(w7, a7.x, acc.x); acc.y = fmaf(w7, a7.y, acc.y);
            acc.z = fmaf(w7, a7.z, acc.z); acc.w = fmaf(w7, a7.w, acc.w);
        }

        float4 o;
        o.x = fmaxf(acc.x + bv.x, 0.f);
        o.y = fmaxf(acc.y + bv.y, 0.f);
        o.z = fmaxf(acc.z + bv.z, 0.f);
        o.w = fmaxf(acc.w + bv.w, 0.f);
        ((float4*)(tb + (size_t)n * FDIM))[lane] = o;
        s[0] += o.x; q[0] += o.x * o.x;
        s[1] += o.y; q[1] += o.y * o.y;
        s[2] += o.z; q[2] += o.z * o.z;
        s[3] += o.w; q[3] += o.w * o.w;
    }

    __shared__ float sh[256 * 8];
    #pragma unroll
    for (int j = 0; j < 4; j++) { sh[tid * 8 + j] = s[j]; sh[tid * 8 + 4 + j] = q[j]; }
    __syncthreads();
    if (tid < 32) {
        float as[4] = {0.f, 0.f, 0.f, 0.f}, aq[4] = {0.f, 0.f, 0.f, 0.f};
        for (int w = 0; w < 8; w++) {
            int src = (tid + 32 * w) * 8;
            #pragma unroll
            for (int j = 0; j < 4; j++) { as[j] += sh[src + j]; aq[j] += sh[src + 4 + j]; }
        }
        #pragma unroll
        for (int j = 0; j < 4; j++) {
            atomicAdd(&gsum[4 * tid + j], as[j]);
            atomicAdd(&gsq [4 * tid + j], aq[j]);
        }
    }
}

// ---------------- fold BN into next weight matrix ----------------------------
__global__ void k_fold(const float* __restrict__ gsum, const float* __restrict__ gsq,
                       const float* __restrict__ gamma, const float* __restrict__ beta,
                       const float* __restrict__ Wsrc, int J,
                       const float* __restrict__ extra_bias,
                       float* __restrict__ Wp, float* __restrict__ cv) {
    __shared__ float ssc[FDIM], ssh[FDIM];
    int t = threadIdx.x;  // 128
    float mu = gsum[t] * (1.0f / M_ROWS);
    float var = gsq[t] * (1.0f / M_ROWS) - mu * mu;
    float sc = gamma[t] * rsqrtf(var + EPSBN);
    ssc[t] = sc;
    ssh[t] = beta[t] - mu * sc;
    __syncthreads();
    if (t < J) {
        float acc = extra_bias ? extra_bias[t] : 0.f;
        for (int k = 0; k < FDIM; k++) {
            float w = Wsrc[k * J + t];
            Wp[k * J + t] = ssc[k] * w;
            acc += ssh[k] * w;
        }
        cv[t] = acc;
    }
}

// ---------------- classifier: out = t2 @ Wcp + bcp ---------------------------
__global__ void k_classifier(const float* __restrict__ t2, const float* __restrict__ Wcp,
                             const float* __restrict__ bcp, float* __restrict__ out) {
    __shared__ float sWT[OUT_DIM * FDIM];  // [o][k]
    __shared__ float sb[OUT_DIM];
    int tid = threadIdx.x;  // 256
    for (int i = tid; i < FDIM * OUT_DIM; i += 256) {
        int k = i / OUT_DIM, o = i % OUT_DIM;
        sWT[o * FDIM + k] = Wcp[i];
    }
    if (tid < OUT_DIM) sb[tid] = bcp[tid];
    __syncthreads();

    int gt = blockIdx.x * blockDim.x + tid;
    int warp = gt >> 5;
    int lane = gt & 31;
    int nw = (gridDim.x * blockDim.x) >> 5;
    for (int rowM = warp; rowM < M_ROWS; rowM += nw) {
        float4 v = __ldg((const float4*)(t2 + (size_t)rowM * FDIM) + lane);
        float y[OUT_DIM];
        #pragma unroll
        for (int o = 0; o < OUT_DIM; o++) {
            float4 w = ((const float4*)(sWT + o * FDIM))[lane];
            y[o] = v.x * w.x + v.y * w.y + v.z * w.z + v.w * w.w;
        }
        #pragma unroll
        for (int off = 16; off; off >>= 1)
            #pragma unroll
            for (int o = 0; o < OUT_DIM; o++)
                y[o] += __shfl_xor_sync(0xffffffffu, y[o], off);
        if (lane < OUT_DIM) out[(size_t)rowM * OUT_DIM + lane] = y[lane] + sb[lane];
    }
}

// ---------------- launch -----------------------------------------------------
extern "C" void kernel_launch(void* const* d_in, const int* in_sizes, int n_in,
                              void* d_out, int out_size) {
    const float* x   = (const float*)d_in[0];
    const int*   ei  = (const int*)d_in[1];
    const float* ewp = (const float*)d_in[2];
    const float* W1  = (const float*)d_in[3];
    const float* b1  = (const float*)d_in[4];
    const float* W2  = (const float*)d_in[5];
    const float* b2  = (const float*)d_in[6];
    const float* g1  = (const float*)d_in[7];
    const float* be1 = (const float*)d_in[8];
    const float* g2  = (const float*)d_in[9];
    const float* be2 = (const float*)d_in[10];
    const float* Wc  = (const float*)d_in[11];
    const float* bc  = (const float*)d_in[12];
    float* out = (float*)d_out;
    const int* row = ei;
    const int* col = ei + N_EDGES;

    float *p_xw, *p_t, *p_dinv, *p_deg;
    float *p_W2p, *p_cvec, *p_Wcp, *p_bcp, *p_sum, *p_sq;
    int *p_cnt, *p_start, *p_cursor, *p_partial, *p_pscan;
    uint2* p_edge;
    cudaGetSymbolAddress((void**)&p_xw,   g_xw);
    cudaGetSymbolAddress((void**)&p_t,    g_t);
    cudaGetSymbolAddress((void**)&p_dinv, g_dinv);
    cudaGetSymbolAddress((void**)&p_deg,  g_deg);
    cudaGetSymbolAddress((void**)&p_cnt,  g_cnt);
    cudaGetSymbolAddress((void**)&p_start, g_start);
    cudaGetSymbolAddress((void**)&p_cursor, g_cursor);
    cudaGetSymbolAddress((void**)&p_partial, g_partial);
    cudaGetSymbolAddress((void**)&p_pscan, g_pscan);
    cudaGetSymbolAddress((void**)&p_edge, g_edge);
    cudaGetSymbolAddress((void**)&p_W2p,  g_W2p);
    cudaGetSymbolAddress((void**)&p_cvec, g_cvec);
    cudaGetSymbolAddress((void**)&p_Wcp,  g_Wcp);
    cudaGetSymbolAddress((void**)&p_bcp,  g_bcp);
    cudaGetSymbolAddress((void**)&p_sum,  g_sum);
    cudaGetSymbolAddress((void**)&p_sq,   g_sq);

    (void)cudaFuncSetAttribute(k_gemm128, cudaFuncAttributeMaxDynamicSharedMemorySize, 98304);

    const size_t batchOff = (size_t)N_NODES * FDIM;

    // --- CSR build + normalization (padded to 8-edge groups) ---
    k_init      <<<(N_NODES + 255) / 256, 256>>>(p_deg, p_cnt);
    k_pass1     <<<(N_EDGES + 255) / 256, 256>>>(ewp, col, p_deg, p_cnt);
    k_dinv      <<<(N_NODES + 255) / 256, 256>>>(p_deg, p_dinv);
    k_scan1     <<<NBLK_SCAN, 256>>>(p_cnt, p_partial);
    k_scan2     <<<1, 256>>>(p_partial, p_pscan, p_start);
    k_scan3     <<<NBLK_SCAN, 256>>>(p_cnt, p_pscan, p_start, p_cursor);
    k_padfill   <<<NBLK_SCAN, 256>>>(p_cnt, p_start, p_edge);
    k_sortedges <<<(N_EDGES + 255) / 256, 256>>>(ewp, row, col, p_dinv, p_cursor, p_edge);

    // --- layer 1 ---
    k_gemm128<<<592, 256, 98304>>>(x, W1, nullptr, p_xw, M_ROWS);
    cudaMemsetAsync(p_sum, 0, FDIM * sizeof(float), 0);
    cudaMemsetAsync(p_sq,  0, FDIM * sizeof(float), 0);
    k_agg<<<1184, 256>>>(p_xw,            p_edge, p_start, p_dinv, b1, p_t,            p_sum, p_sq);
    k_agg<<<1184, 256>>>(p_xw + batchOff, p_edge, p_start, p_dinv, b1, p_t + batchOff, p_sum, p_sq);
    k_fold<<<1, 128>>>(p_sum, p_sq, g1, be1, W2, FDIM, nullptr, p_W2p, p_cvec);

    // --- layer 2 (BN1 folded into W2) ---
    k_gemm128<<<592, 256, 98304>>>(p_t, p_W2p, p_cvec, p_xw, M_ROWS);
    cudaMemsetAsync(p_sum, 0, FDIM * sizeof(float), 0);
    cudaMemsetAsync(p_sq,  0, FDIM * sizeof(float), 0);
    k_agg<<<1184, 256>>>(p_xw,            p_edge, p_start, p_dinv, b2, p_t,            p_sum, p_sq);
    k_agg<<<1184, 256>>>(p_xw + batchOff, p_edge, p_start, p_dinv, b2, p_t + batchOff, p_sum, p_sq);
    k_fold<<<1, 128>>>(p_sum, p_sq, g2, be2, Wc, OUT_DIM, bc, p_Wcp, p_bcp);

    // --- classifier (BN2 folded into Wc) ---
    k_classifier<<<1024, 256>>>(p_t, p_Wcp, p_bcp, out);
}

// round 5
// speedup vs baseline: 1.4561x; 1.4561x over previous
#include <cuda_runtime.h>

#define N_NODES 50000
#define N_EDGES 640000
#define FDIM    128
#define OUT_DIM 16
#define BATCH   2
#define M_ROWS  (BATCH * N_NODES)   /* 100000 flattened rows */
#define EPSBN   1e-5f
#define NBLK_SCAN ((N_NODES + 255) / 256)   /* 196 */

// ---------------- scratch (device globals; no allocation allowed) -------------
__device__ __align__(128) float g_xw  [(size_t)M_ROWS * FDIM];  // GEMM outputs
__device__ __align__(128) float g_t   [(size_t)M_ROWS * FDIM];  // relu(conv) activations
__device__ __align__(128) float g_dinv[N_NODES];
__device__ __align__(128) float g_deg [N_NODES];
__device__ __align__(128) int   g_cnt   [N_NODES];
__device__ __align__(128) int   g_start [N_NODES + 1];
__device__ __align__(128) int   g_cursor[N_NODES];
__device__ __align__(128) int   g_partial[256];
__device__ __align__(128) int   g_pscan  [256];
__device__ __align__(128) uint2 g_edge  [N_EDGES];              // {src, norm-bits} sorted by dst
__device__ __align__(128) float g_W2p [FDIM * FDIM];
__device__ __align__(128) float g_cvec[FDIM];
__device__ __align__(128) float g_Wcp [FDIM * OUT_DIM];
__device__ __align__(128) float g_bcp [OUT_DIM];
__device__ __align__(128) float g_sum [FDIM];
__device__ __align__(128) float g_sq  [FDIM];

// ---------------- init: deg=1 (self loop), cnt=0 ----------------------------
__global__ void k_init(float* deg, int* cnt) {
    int i = blockIdx.x * blockDim.x + threadIdx.x;
    if (i < N_NODES) { deg[i] = 1.0f; cnt[i] = 0; }
}

// ---------------- pass1: degree accumulation + dst histogram -----------------
__global__ void k_pass1(const float* __restrict__ ewp, const int* __restrict__ col,
                        float* deg, int* cnt) {
    int e = blockIdx.x * blockDim.x + threadIdx.x;
    if (e < N_EDGES) {
        int c = col[e];
        atomicAdd(&deg[c], expf(ewp[e]));
        atomicAdd(&cnt[c], 1);
    }
}

__global__ void k_dinv(const float* __restrict__ deg, float* dinv) {
    int i = blockIdx.x * blockDim.x + threadIdx.x;
    if (i < N_NODES) {
        float d = deg[i];
        dinv[i] = (d > 0.f) ? rsqrtf(d) : 0.f;
    }
}

// ---------------- hierarchical scan (3 kernels, all coalesced) ---------------
__global__ void k_scan1(const int* __restrict__ cnt, int* __restrict__ partial) {
    __shared__ int sh[8];
    int idx = blockIdx.x * 256 + threadIdx.x;
    int v = (idx < N_NODES) ? cnt[idx] : 0;
    #pragma unroll
    for (int off = 16; off; off >>= 1) v += __shfl_down_sync(0xffffffffu, v, off);
    if ((threadIdx.x & 31) == 0) sh[threadIdx.x >> 5] = v;
    __syncthreads();
    if (threadIdx.x == 0) {
        int s = 0;
        #pragma unroll
        for (int w = 0; w < 8; w++) s += sh[w];
        partial[blockIdx.x] = s;
    }
}

__global__ void k_scan2(const int* __restrict__ partial, int* __restrict__ pscan,
                        int* __restrict__ start) {
    __shared__ int sh[256];
    int t = threadIdx.x;
    int v = (t < NBLK_SCAN) ? partial[t] : 0;
    sh[t] = v;
    __syncthreads();
    #pragma unroll
    for (int off = 1; off < 256; off <<= 1) {
        int u = (t >= off) ? sh[t - off] : 0;
        __syncthreads();
        sh[t] += u;
        __syncthreads();
    }
    if (t < NBLK_SCAN) pscan[t] = sh[t] - v;   // exclusive
    if (t == 0) start[N_NODES] = N_EDGES;
}

__global__ void k_scan3(const int* __restrict__ cnt, const int* __restrict__ pscan,
                        int* __restrict__ start, int* __restrict__ cursor) {
    __shared__ int sh[256];
    int t = threadIdx.x;
    int idx = blockIdx.x * 256 + t;
    int v = (idx < N_NODES) ? cnt[idx] : 0;
    sh[t] = v;
    __syncthreads();
    #pragma unroll
    for (int off = 1; off < 256; off <<= 1) {
        int u = (t >= off) ? sh[t - off] : 0;
        __syncthreads();
        sh[t] += u;
        __syncthreads();
    }
    if (idx < N_NODES) {
        int excl = sh[t] - v + pscan[blockIdx.x];
        start[idx] = excl;
        cursor[idx] = excl;
    }
}

// ---------------- bucket scatter: sorted {src, norm} per destination ---------
__global__ void k_sortedges(const float* __restrict__ ewp, const int* __restrict__ row,
                            const int* __restrict__ col, const float* __restrict__ dinv,
                            int* cursor, uint2* __restrict__ edge) {
    int e = blockIdx.x * blockDim.x + threadIdx.x;
    if (e < N_EDGES) {
        int r = row[e];
        int c = col[e];
        float nm = dinv[r] * expf(ewp[e]) * dinv[c];
        int pos = atomicAdd(&cursor[c], 1);
        edge[pos] = make_uint2((unsigned)r, __float_as_uint(nm));
    }
}

// ---------------- GEMM: C[M x128] = A[M x128] @ W[128x128] (+ cvec) ----------
__global__ __launch_bounds__(256) void k_gemm128(const float* __restrict__ A,
                                                 const float* __restrict__ W,
                                                 const float* __restrict__ cvec,
                                                 float* __restrict__ C, int Mrows) {
    extern __shared__ float smem[];
    float* sW = smem;            // 128*128 floats = 64 KB
    float* sA = smem + 16384;    // 64*128 floats = 32 KB
    const int tid = threadIdx.x;

    {   // load W once per block
        const float4* W4 = (const float4*)W;
        float4* sW4 = (float4*)sW;
        #pragma unroll
        for (int i = 0; i < 16; i++) sW4[tid + i * 256] = W4[tid + i * 256];
    }

    const int tc = tid & 15;   // cols 8*tc .. 8*tc+7
    const int tr = tid >> 4;   // rows 4*tr .. 4*tr+3

    unsigned long long initc[4];
    if (cvec) {
        #pragma unroll
        for (int p = 0; p < 4; p++) {
            float2 cv2 = *(const float2*)(cvec + 8 * tc + 2 * p);
            asm("mov.b64 %0, {%1, %2};" : "=l"(initc[p]) : "f"(cv2.x), "f"(cv2.y));
        }
    } else {
        #pragma unroll
        for (int p = 0; p < 4; p++) initc[p] = 0ull;
    }

    const int ntiles = (Mrows + 63) >> 6;
    for (int tile = blockIdx.x; tile < ntiles; tile += gridDim.x) {
        const int base = tile << 6;
        __syncthreads();
        #pragma unroll
        for (int i = 0; i < 8; i++) {
            int f4 = tid + i * 256;
            int r = f4 >> 5;
            int c4 = f4 & 31;
            int grow = base + r;
            float4 v = make_float4(0.f, 0.f, 0.f, 0.f);
            if (grow < Mrows) v = ((const float4*)A)[(size_t)grow * 32 + c4];
            ((float4*)sA)[f4] = v;
        }
        __syncthreads();

        unsigned long long acc[4][4];
        #pragma unroll
        for (int r = 0; r < 4; r++)
            #pragma unroll
            for (int p = 0; p < 4; p++) acc[r][p] = initc[p];

        const float* aBase = sA + (tr << 2) * FDIM;
        #pragma unroll 2
        for (int k0 = 0; k0 < FDIM; k0 += 4) {
            float4 a0 = *(const float4*)(aBase + k0);
            float4 a1 = *(const float4*)(aBase + FDIM + k0);
            float4 a2 = *(const float4*)(aBase + 2 * FDIM + k0);
            float4 a3 = *(const float4*)(aBase + 3 * FDIM + k0);
            float am[4][4] = {{a0.x, a0.y, a0.z, a0.w}, {a1.x, a1.y, a1.z, a1.w},
                              {a2.x, a2.y, a2.z, a2.w}, {a3.x, a3.y, a3.z, a3.w}};
            #pragma unroll
            for (int kk = 0; kk < 4; kk++) {
                const ulonglong2* bp = (const ulonglong2*)(sW + (k0 + kk) * FDIM + (tc << 3));
                ulonglong2 b01 = bp[0];
                ulonglong2 b23 = bp[1];
                unsigned long long bv[4] = {b01.x, b01.y, b23.x, b23.y};
                unsigned long long pa[4];
                #pragma unroll
                for (int r = 0; r < 4; r++)
                    asm("mov.b64 %0, {%1, %1};" : "=l"(pa[r]) : "f"(am[r][kk]));
                #pragma unroll
                for (int r = 0; r < 4; r++)
                    #pragma unroll
                    for (int p = 0; p < 4; p++)
                        asm("fma.rn.f32x2 %0, %1, %2, %0;"
                            : "+l"(acc[r][p]) : "l"(pa[r]), "l"(bv[p]));
            }
        }

        #pragma unroll
        for (int r = 0; r < 4; r++) {
            int grow = base + (tr << 2) + r;
            if (grow < Mrows) {
                ulonglong2* cp = (ulonglong2*)(C + (size_t)grow * FDIM + (tc << 3));
                cp[0] = make_ulonglong2(acc[r][0], acc[r][1]);
                cp[1] = make_ulonglong2(acc[r][2], acc[r][3]);
            }
        }
    }
}

// ---------------- fused aggregate + self-loop + bias + relu + BN stats -------
// ONE batch per launch; warp per node; double-buffered pipeline: next group's
// metadata AND gathers are issued before current group's FMAs consume results
// -> 8 row-gathers in flight steady-state, zero extra traffic.
__global__ __launch_bounds__(256) void k_agg(const float* __restrict__ xwb,
                                             const uint2* __restrict__ edge,
                                             const int* __restrict__ start,
                                             const float* __restrict__ dinv,
                                             const float* __restrict__ bias,
                                             float* __restrict__ tb,
                                             float* __restrict__ gsum,
                                             float* __restrict__ gsq) {
    const int tid = threadIdx.x;
    const int lane = tid & 31;
    const int gw = (blockIdx.x * blockDim.x + tid) >> 5;
    const int nwarps = (gridDim.x * blockDim.x) >> 5;
    const float4 bv = ((const float4*)bias)[lane];
    float s[4] = {0.f, 0.f, 0.f, 0.f}, q[4] = {0.f, 0.f, 0.f, 0.f};

    for (int n = gw; n < N_NODES; n += nwarps) {
        const int st = start[n];
        const int en = start[n + 1];
        const float d = dinv[n];
        const float d2 = d * d;
        float4 v = __ldg((const float4*)(xwb + (size_t)n * FDIM) + lane);
        float4 acc = make_float4(d2 * v.x, d2 * v.y, d2 * v.z, d2 * v.w);

        const int cnt4 = (en - st) >> 2;
        int e = st;
        if (cnt4 > 0) {
            // prologue: group 0 meta + gathers
            uint2 m0 = __ldg(&edge[e]);
            uint2 m1 = __ldg(&edge[e + 1]);
            uint2 m2 = __ldg(&edge[e + 2]);
            uint2 m3 = __ldg(&edge[e + 3]);
            float4 a0 = __ldg((const float4*)(xwb + (size_t)m0.x * FDIM) + lane);
            float4 a1 = __ldg((const float4*)(xwb + (size_t)m1.x * FDIM) + lane);
            float4 a2 = __ldg((const float4*)(xwb + (size_t)m2.x * FDIM) + lane);
            float4 a3 = __ldg((const float4*)(xwb + (size_t)m3.x * FDIM) + lane);
            for (int g = 1; g < cnt4; g++) {
                const int ne = e + 4;
                // next group: meta then gathers, issued BEFORE current FMAs
                uint2 p0 = __ldg(&edge[ne]);
                uint2 p1 = __ldg(&edge[ne + 1]);
                uint2 p2 = __ldg(&edge[ne + 2]);
                uint2 p3 = __ldg(&edge[ne + 3]);
                float4 n0 = __ldg((const float4*)(xwb + (size_t)p0.x * FDIM) + lane);
                float4 n1 = __ldg((const float4*)(xwb + (size_t)p1.x * FDIM) + lane);
                float4 n2 = __ldg((const float4*)(xwb + (size_t)p2.x * FDIM) + lane);
                float4 n3 = __ldg((const float4*)(xwb + (size_t)p3.x * FDIM) + lane);
                // consume current group
                float w0 = __uint_as_float(m0.y), w1 = __uint_as_float(m1.y);
                float w2 = __uint_as_float(m2.y), w3 = __uint_as_float(m3.y);
                acc.x = fmaf(w0, a0.x, acc.x); acc.y = fmaf(w0, a0.y, acc.y);
                acc.z = fmaf(w0, a0.z, acc.z); acc.w = fmaf(w0, a0.w, acc.w);
                acc.x = fmaf(w1, a1.x, acc.x); acc.y = fmaf(w1, a1.y, acc.y);
                acc.z = fmaf(w1, a1.z, acc.z); acc.w = fmaf(w1, a1.w, acc.w);
                acc.x = fmaf(w2, a2.x, acc.x); acc.y = fmaf(w2, a2.y, acc.y);
                acc.z = fmaf(w2, a2.z, acc.z); acc.w = fmaf(w2, a2.w, acc.w);
                acc.x = fmaf(w3, a3.x, acc.x); acc.y = fmaf(w3, a3.y, acc.y);
                acc.z = fmaf(w3, a3.z, acc.z); acc.w = fmaf(w3, a3.w, acc.w);
                m0 = p0; m1 = p1; m2 = p2; m3 = p3;
                a0 = n0; a1 = n1; a2 = n2; a3 = n3;
                e = ne;
            }
            // epilogue: last group
            {
                float w0 = __uint_as_float(m0.y), w1 = __uint_as_float(m1.y);
                float w2 = __uint_as_float(m2.y), w3 = __uint_as_float(m3.y);
                acc.x = fmaf(w0, a0.x, acc.x); acc.y = fmaf(w0, a0.y, acc.y);
                acc.z = fmaf(w0, a0.z, acc.z); acc.w = fmaf(w0, a0.w, acc.w);
                acc.x = fmaf(w1, a1.x, acc.x); acc.y = fmaf(w1, a1.y, acc.y);
                acc.z = fmaf(w1, a1.z, acc.z); acc.w = fmaf(w1, a1.w, acc.w);
                acc.x = fmaf(w2, a2.x, acc.x); acc.y = fmaf(w2, a2.y, acc.y);
                acc.z = fmaf(w2, a2.z, acc.z); acc.w = fmaf(w2, a2.w, acc.w);
                acc.x = fmaf(w3, a3.x, acc.x); acc.y = fmaf(w3, a3.y, acc.y);
                acc.z = fmaf(w3, a3.z, acc.z); acc.w = fmaf(w3, a3.w, acc.w);
            }
            e = st + (cnt4 << 2);
        }
        for (; e < en; e++) {
            uint2 m = __ldg(&edge[e]);
            float4 a = __ldg((const float4*)(xwb + (size_t)m.x * FDIM) + lane);
            float w = __uint_as_float(m.y);
            acc.x = fmaf(w, a.x, acc.x); acc.y = fmaf(w, a.y, acc.y);
            acc.z = fmaf(w, a.z, acc.z); acc.w = fmaf(w, a.w, acc.w);
        }

        float4 o;
        o.x = fmaxf(acc.x + bv.x, 0.f);
        o.y = fmaxf(acc.y + bv.y, 0.f);
        o.z = fmaxf(acc.z + bv.z, 0.f);
        o.w = fmaxf(acc.w + bv.w, 0.f);
        ((float4*)(tb + (size_t)n * FDIM))[lane] = o;
        s[0] += o.x; q[0] += o.x * o.x;
        s[1] += o.y; q[1] += o.y * o.y;
        s[2] += o.z; q[2] += o.z * o.z;
        s[3] += o.w; q[3] += o.w * o.w;
    }

    __shared__ float sh[256 * 8];
    #pragma unroll
    for (int j = 0; j < 4; j++) { sh[tid * 8 + j] = s[j]; sh[tid * 8 + 4 + j] = q[j]; }
    __syncthreads();
    if (tid < 32) {
        float as[4] = {0.f, 0.f, 0.f, 0.f}, aq[4] = {0.f, 0.f, 0.f, 0.f};
        for (int w = 0; w < 8; w++) {
            int src = (tid + 32 * w) * 8;
            #pragma unroll
            for (int j = 0; j < 4; j++) { as[j] += sh[src + j]; aq[j] += sh[src + 4 + j]; }
        }
        #pragma unroll
        for (int j = 0; j < 4; j++) {
            atomicAdd(&gsum[4 * tid + j], as[j]);
            atomicAdd(&gsq [4 * tid + j], aq[j]);
        }
    }
}

// ---------------- fold BN into next weight matrix ----------------------------
__global__ void k_fold(const float* __restrict__ gsum, const float* __restrict__ gsq,
                       const float* __restrict__ gamma, const float* __restrict__ beta,
                       const float* __restrict__ Wsrc, int J,
                       const float* __restrict__ extra_bias,
                       float* __restrict__ Wp, float* __restrict__ cv) {
    __shared__ float ssc[FDIM], ssh[FDIM];
    int t = threadIdx.x;  // 128
    float mu = gsum[t] * (1.0f / M_ROWS);
    float var = gsq[t] * (1.0f / M_ROWS) - mu * mu;
    float sc = gamma[t] * rsqrtf(var + EPSBN);
    ssc[t] = sc;
    ssh[t] = beta[t] - mu * sc;
    __syncthreads();
    if (t < J) {
        float acc = extra_bias ? extra_bias[t] : 0.f;
        for (int k = 0; k < FDIM; k++) {
            float w = Wsrc[k * J + t];
            Wp[k * J + t] = ssc[k] * w;
            acc += ssh[k] * w;
        }
        cv[t] = acc;
    }
}

// ---------------- classifier: out = t2 @ Wcp + bcp ---------------------------
__global__ void k_classifier(const float* __restrict__ t2, const float* __restrict__ Wcp,
                             const float* __restrict__ bcp, float* __restrict__ out) {
    __shared__ float sWT[OUT_DIM * FDIM];  // [o][k]
    __shared__ float sb[OUT_DIM];
    int tid = threadIdx.x;  // 256
    for (int i = tid; i < FDIM * OUT_DIM; i += 256) {
        int k = i / OUT_DIM, o = i % OUT_DIM;
        sWT[o * FDIM + k] = Wcp[i];
    }
    if (tid < OUT_DIM) sb[tid] = bcp[tid];
    __syncthreads();

    int gt = blockIdx.x * blockDim.x + tid;
    int warp = gt >> 5;
    int lane = gt & 31;
    int nw = (gridDim.x * blockDim.x) >> 5;
    for (int rowM = warp; rowM < M_ROWS; rowM += nw) {
        float4 v = __ldg((const float4*)(t2 + (size_t)rowM * FDIM) + lane);
        float y[OUT_DIM];
        #pragma unroll
        for (int o = 0; o < OUT_DIM; o++) {
            float4 w = ((const float4*)(sWT + o * FDIM))[lane];
            y[o] = v.x * w.x + v.y * w.y + v.z * w.z + v.w * w.w;
        }
        #pragma unroll
        for (int off = 16; off; off >>= 1)
            #pragma unroll
            for (int o = 0; o < OUT_DIM; o++)
                y[o] += __shfl_xor_sync(0xffffffffu, y[o], off);
        if (lane < OUT_DIM) out[(size_t)rowM * OUT_DIM + lane] = y[lane] + sb[lane];
    }
}

// ---------------- launch -----------------------------------------------------
extern "C" void kernel_launch(void* const* d_in, const int* in_sizes, int n_in,
                              void* d_out, int out_size) {
    const float* x   = (const float*)d_in[0];
    const int*   ei  = (const int*)d_in[1];
    const float* ewp = (const float*)d_in[2];
    const float* W1  = (const float*)d_in[3];
    const float* b1  = (const float*)d_in[4];
    const float* W2  = (const float*)d_in[5];
    const float* b2  = (const float*)d_in[6];
    const float* g1  = (const float*)d_in[7];
    const float* be1 = (const float*)d_in[8];
    const float* g2  = (const float*)d_in[9];
    const float* be2 = (const float*)d_in[10];
    const float* Wc  = (const float*)d_in[11];
    const float* bc  = (const float*)d_in[12];
    float* out = (float*)d_out;
    const int* row = ei;
    const int* col = ei + N_EDGES;

    float *p_xw, *p_t, *p_dinv, *p_deg;
    float *p_W2p, *p_cvec, *p_Wcp, *p_bcp, *p_sum, *p_sq;
    int *p_cnt, *p_start, *p_cursor, *p_partial, *p_pscan;
    uint2* p_edge;
    cudaGetSymbolAddress((void**)&p_xw,   g_xw);
    cudaGetSymbolAddress((void**)&p_t,    g_t);
    cudaGetSymbolAddress((void**)&p_dinv, g_dinv);
    cudaGetSymbolAddress((void**)&p_deg,  g_deg);
    cudaGetSymbolAddress((void**)&p_cnt,  g_cnt);
    cudaGetSymbolAddress((void**)&p_start, g_start);
    cudaGetSymbolAddress((void**)&p_cursor, g_cursor);
    cudaGetSymbolAddress((void**)&p_partial, g_partial);
    cudaGetSymbolAddress((void**)&p_pscan, g_pscan);
    cudaGetSymbolAddress((void**)&p_edge, g_edge);
    cudaGetSymbolAddress((void**)&p_W2p,  g_W2p);
    cudaGetSymbolAddress((void**)&p_cvec, g_cvec);
    cudaGetSymbolAddress((void**)&p_Wcp,  g_Wcp);
    cudaGetSymbolAddress((void**)&p_bcp,  g_bcp);
    cudaGetSymbolAddress((void**)&p_sum,  g_sum);
    cudaGetSymbolAddress((void**)&p_sq,   g_sq);

    (void)cudaFuncSetAttribute(k_gemm128, cudaFuncAttributeMaxDynamicSharedMemorySize, 98304);

    const size_t batchOff = (size_t)N_NODES * FDIM;

    // --- CSR build + normalization ---
    k_init      <<<(N_NODES + 255) / 256, 256>>>(p_deg, p_cnt);
    k_pass1     <<<(N_EDGES + 255) / 256, 256>>>(ewp, col, p_deg, p_cnt);
    k_dinv      <<<(N_NODES + 255) / 256, 256>>>(p_deg, p_dinv);
    k_scan1     <<<NBLK_SCAN, 256>>>(p_cnt, p_partial);
    k_scan2     <<<1, 256>>>(p_partial, p_pscan, p_start);
    k_scan3     <<<NBLK_SCAN, 256>>>(p_cnt, p_pscan, p_start, p_cursor);
    k_sortedges <<<(N_EDGES + 255) / 256, 256>>>(ewp, row, col, p_dinv, p_cursor, p_edge);

    // --- layer 1 ---
    k_gemm128<<<592, 256, 98304>>>(x, W1, nullptr, p_xw, M_ROWS);
    cudaMemsetAsync(p_sum, 0, FDIM * sizeof(float), 0);
    cudaMemsetAsync(p_sq,  0, FDIM * sizeof(float), 0);
    k_agg<<<1184, 256>>>(p_xw,            p_edge, p_start, p_dinv, b1, p_t,            p_sum, p_sq);
    k_agg<<<1184, 256>>>(p_xw + batchOff, p_edge, p_start, p_dinv, b1, p_t + batchOff, p_sum, p_sq);
    k_fold<<<1, 128>>>(p_sum, p_sq, g1, be1, W2, FDIM, nullptr, p_W2p, p_cvec);

    // --- layer 2 (BN1 folded into W2) ---
    k_gemm128<<<592, 256, 98304>>>(p_t, p_W2p, p_cvec, p_xw, M_ROWS);
    cudaMemsetAsync(p_sum, 0, FDIM * sizeof(float), 0);
    cudaMemsetAsync(p_sq,  0, FDIM * sizeof(float), 0);
    k_agg<<<1184, 256>>>(p_xw,            p_edge, p_start, p_dinv, b2, p_t,            p_sum, p_sq);
    k_agg<<<1184, 256>>>(p_xw + batchOff, p_edge, p_start, p_dinv, b2, p_t + batchOff, p_sum, p_sq);
    k_fold<<<1, 128>>>(p_sum, p_sq, g2, be2, Wc, OUT_DIM, bc, p_Wcp, p_bcp);

    // --- classifier (BN2 folded into Wc) ---
    k_classifier<<<1024, 256>>>(p_t, p_Wcp, p_bcp, out);
}

// round 6
// speedup vs baseline: 1.7506x; 1.2022x over previous
#include <cuda_runtime.h>

#define N_NODES 50000
#define N_EDGES 640000
#define FDIM    128
#define OUT_DIM 16
#define BATCH   2
#define M_ROWS  (BATCH * N_NODES)   /* 100000 flattened rows */
#define EPSBN   1e-5f
#define NBLK_SCAN ((N_NODES + 255) / 256)   /* 196 */

// ---------------- scratch (device globals; no allocation allowed) -------------
__device__ __align__(128) float g_xw  [(size_t)M_ROWS * FDIM];  // GEMM outputs (interleaved [n][b][128])
__device__ __align__(128) float g_t   [(size_t)M_ROWS * FDIM];  // relu(conv) activations (interleaved)
__device__ __align__(128) float g_dinv[N_NODES];
__device__ __align__(128) float g_deg [N_NODES];
__device__ __align__(128) int   g_cnt   [N_NODES];
__device__ __align__(128) int   g_start [N_NODES + 1];
__device__ __align__(128) int   g_cursor[N_NODES];
__device__ __align__(128) int   g_partial[256];
__device__ __align__(128) int   g_pscan  [256];
__device__ __align__(128) uint2 g_edge  [N_EDGES];              // {src, norm-bits} sorted by dst
__device__ __align__(128) float g_W2p [FDIM * FDIM];
__device__ __align__(128) float g_cvec[FDIM];
__device__ __align__(128) float g_Wcp [FDIM * OUT_DIM];
__device__ __align__(128) float g_bcp [OUT_DIM];
__device__ __align__(128) float g_sum [FDIM];
__device__ __align__(128) float g_sq  [FDIM];

// ---------------- init: deg=1 (self loop), cnt=0 ----------------------------
__global__ void k_init(float* deg, int* cnt) {
    int i = blockIdx.x * blockDim.x + threadIdx.x;
    if (i < N_NODES) { deg[i] = 1.0f; cnt[i] = 0; }
}

// ---------------- pass1: degree accumulation + dst histogram -----------------
__global__ void k_pass1(const float* __restrict__ ewp, const int* __restrict__ col,
                        float* deg, int* cnt) {
    int e = blockIdx.x * blockDim.x + threadIdx.x;
    if (e < N_EDGES) {
        int c = col[e];
        atomicAdd(&deg[c], expf(ewp[e]));
        atomicAdd(&cnt[c], 1);
    }
}

__global__ void k_dinv(const float* __restrict__ deg, float* dinv) {
    int i = blockIdx.x * blockDim.x + threadIdx.x;
    if (i < N_NODES) {
        float d = deg[i];
        dinv[i] = (d > 0.f) ? rsqrtf(d) : 0.f;
    }
}

// ---------------- hierarchical scan (3 kernels, all coalesced) ---------------
__global__ void k_scan1(const int* __restrict__ cnt, int* __restrict__ partial) {
    __shared__ int sh[8];
    int idx = blockIdx.x * 256 + threadIdx.x;
    int v = (idx < N_NODES) ? cnt[idx] : 0;
    #pragma unroll
    for (int off = 16; off; off >>= 1) v += __shfl_down_sync(0xffffffffu, v, off);
    if ((threadIdx.x & 31) == 0) sh[threadIdx.x >> 5] = v;
    __syncthreads();
    if (threadIdx.x == 0) {
        int s = 0;
        #pragma unroll
        for (int w = 0; w < 8; w++) s += sh[w];
        partial[blockIdx.x] = s;
    }
}

__global__ void k_scan2(const int* __restrict__ partial, int* __restrict__ pscan,
                        int* __restrict__ start) {
    __shared__ int sh[256];
    int t = threadIdx.x;
    int v = (t < NBLK_SCAN) ? partial[t] : 0;
    sh[t] = v;
    __syncthreads();
    #pragma unroll
    for (int off = 1; off < 256; off <<= 1) {
        int u = (t >= off) ? sh[t - off] : 0;
        __syncthreads();
        sh[t] += u;
        __syncthreads();
    }
    if (t < NBLK_SCAN) pscan[t] = sh[t] - v;   // exclusive
    if (t == 0) start[N_NODES] = N_EDGES;
}

__global__ void k_scan3(const int* __restrict__ cnt, const int* __restrict__ pscan,
                        int* __restrict__ start, int* __restrict__ cursor) {
    __shared__ int sh[256];
    int t = threadIdx.x;
    int idx = blockIdx.x * 256 + t;
    int v = (idx < N_NODES) ? cnt[idx] : 0;
    sh[t] = v;
    __syncthreads();
    #pragma unroll
    for (int off = 1; off < 256; off <<= 1) {
        int u = (t >= off) ? sh[t - off] : 0;
        __syncthreads();
        sh[t] += u;
        __syncthreads();
    }
    if (idx < N_NODES) {
        int excl = sh[t] - v + pscan[blockIdx.x];
        start[idx] = excl;
        cursor[idx] = excl;
    }
}

// ---------------- bucket scatter: sorted {src, norm} per destination ---------
__global__ void k_sortedges(const float* __restrict__ ewp, const int* __restrict__ row,
                            const int* __restrict__ col, const float* __restrict__ dinv,
                            int* cursor, uint2* __restrict__ edge) {
    int e = blockIdx.x * blockDim.x + threadIdx.x;
    if (e < N_EDGES) {
        int r = row[e];
        int c = col[e];
        float nm = dinv[r] * expf(ewp[e]) * dinv[c];
        int pos = atomicAdd(&cursor[c], 1);
        edge[pos] = make_uint2((unsigned)r, __float_as_uint(nm));
    }
}

// ---------------- GEMM: C[M x128] = A[M x128] @ W[128x128] (+ cvec) ----------
// remap!=0: output row j corresponds to input row (j&1)*N_NODES + (j>>1)
// (converts harness [b][n] layout into interleaved [n][b] on the fly)
__global__ __launch_bounds__(256) void k_gemm128(const float* __restrict__ A,
                                                 const float* __restrict__ W,
                                                 const float* __restrict__ cvec,
                                                 float* __restrict__ C, int Mrows,
                                                 int remap) {
    extern __shared__ float smem[];
    float* sW = smem;            // 128*128 floats = 64 KB
    float* sA = smem + 16384;    // 64*128 floats = 32 KB
    const int tid = threadIdx.x;

    {   // load W once per block
        const float4* W4 = (const float4*)W;
        float4* sW4 = (float4*)sW;
        #pragma unroll
        for (int i = 0; i < 16; i++) sW4[tid + i * 256] = W4[tid + i * 256];
    }

    const int tc = tid & 15;   // cols 8*tc .. 8*tc+7
    const int tr = tid >> 4;   // rows 4*tr .. 4*tr+3

    unsigned long long initc[4];
    if (cvec) {
        #pragma unroll
        for (int p = 0; p < 4; p++) {
            float2 cv2 = *(const float2*)(cvec + 8 * tc + 2 * p);
            asm("mov.b64 %0, {%1, %2};" : "=l"(initc[p]) : "f"(cv2.x), "f"(cv2.y));
        }
    } else {
        #pragma unroll
        for (int p = 0; p < 4; p++) initc[p] = 0ull;
    }

    const int ntiles = (Mrows + 63) >> 6;
    for (int tile = blockIdx.x; tile < ntiles; tile += gridDim.x) {
        const int base = tile << 6;
        __syncthreads();
        #pragma unroll
        for (int i = 0; i < 8; i++) {
            int f4 = tid + i * 256;
            int r = f4 >> 5;
            int c4 = f4 & 31;
            int grow = base + r;
            float4 v = make_float4(0.f, 0.f, 0.f, 0.f);
            if (grow < Mrows) {
                int irow = remap ? ((grow & 1) * N_NODES + (grow >> 1)) : grow;
                v = ((const float4*)A)[(size_t)irow * 32 + c4];
            }
            ((float4*)sA)[f4] = v;
        }
        __syncthreads();

        unsigned long long acc[4][4];
        #pragma unroll
        for (int r = 0; r < 4; r++)
            #pragma unroll
            for (int p = 0; p < 4; p++) acc[r][p] = initc[p];

        const float* aBase = sA + (tr << 2) * FDIM;
        #pragma unroll 2
        for (int k0 = 0; k0 < FDIM; k0 += 4) {
            float4 a0 = *(const float4*)(aBase + k0);
            float4 a1 = *(const float4*)(aBase + FDIM + k0);
            float4 a2 = *(const float4*)(aBase + 2 * FDIM + k0);
            float4 a3 = *(const float4*)(aBase + 3 * FDIM + k0);
            float am[4][4] = {{a0.x, a0.y, a0.z, a0.w}, {a1.x, a1.y, a1.z, a1.w},
                              {a2.x, a2.y, a2.z, a2.w}, {a3.x, a3.y, a3.z, a3.w}};
            #pragma unroll
            for (int kk = 0; kk < 4; kk++) {
                const ulonglong2* bp = (const ulonglong2*)(sW + (k0 + kk) * FDIM + (tc << 3));
                ulonglong2 b01 = bp[0];
                ulonglong2 b23 = bp[1];
                unsigned long long bv[4] = {b01.x, b01.y, b23.x, b23.y};
                unsigned long long pa[4];
                #pragma unroll
                for (int r = 0; r < 4; r++)
                    asm("mov.b64 %0, {%1, %1};" : "=l"(pa[r]) : "f"(am[r][kk]));
                #pragma unroll
                for (int r = 0; r < 4; r++)
                    #pragma unroll
                    for (int p = 0; p < 4; p++)
                        asm("fma.rn.f32x2 %0, %1, %2, %0;"
                            : "+l"(acc[r][p]) : "l"(pa[r]), "l"(bv[p]));
            }
        }

        #pragma unroll
        for (int r = 0; r < 4; r++) {
            int grow = base + (tr << 2) + r;
            if (grow < Mrows) {
                ulonglong2* cp = (ulonglong2*)(C + (size_t)grow * FDIM + (tc << 3));
                cp[0] = make_ulonglong2(acc[r][0], acc[r][1]);
                cp[1] = make_ulonglong2(acc[r][2], acc[r][3]);
            }
        }
    }
}

// ---------------- fused aggregate (BOTH batches) + self + bias + relu + BN ---
// Interleaved layout [n][b][128]: warp per node, edge meta read once, each
// edge gathers one contiguous 1KB block (both batch rows) -> 8 gathers/group.
__global__ __launch_bounds__(256) void k_agg(const float* __restrict__ xwi,
                                             const uint2* __restrict__ edge,
                                             const int* __restrict__ start,
                                             const float* __restrict__ dinv,
                                             const float* __restrict__ bias,
                                             float* __restrict__ ti,
                                             float* __restrict__ gsum,
                                             float* __restrict__ gsq) {
    const int tid = threadIdx.x;
    const int lane = tid & 31;
    const int gw = (blockIdx.x * blockDim.x + tid) >> 5;
    const int nwarps = (gridDim.x * blockDim.x) >> 5;
    const float4 bv = ((const float4*)bias)[lane];
    float s[4] = {0.f, 0.f, 0.f, 0.f}, q[4] = {0.f, 0.f, 0.f, 0.f};

    for (int n = gw; n < N_NODES; n += nwarps) {
        const int st = start[n];
        const int en = start[n + 1];
        const float d = dinv[n];
        const float d2 = d * d;
        const float4* self = (const float4*)(xwi + (size_t)(2 * n) * FDIM);
        float4 v0 = __ldg(self + lane);
        float4 v1 = __ldg(self + 32 + lane);
        float4 acc0 = make_float4(d2 * v0.x, d2 * v0.y, d2 * v0.z, d2 * v0.w);
        float4 acc1 = make_float4(d2 * v1.x, d2 * v1.y, d2 * v1.z, d2 * v1.w);

        const int cnt4 = (en - st) >> 2;
        int e = st;
        if (cnt4 > 0) {
            uint2 m0 = __ldg(&edge[e]);
            uint2 m1 = __ldg(&edge[e + 1]);
            uint2 m2 = __ldg(&edge[e + 2]);
            uint2 m3 = __ldg(&edge[e + 3]);
            for (int g = 0; g < cnt4; g++) {
                uint2 p0, p1, p2, p3;
                const int ne = e + 4;
                if (g + 1 < cnt4) {             // prefetch next group's metadata
                    p0 = __ldg(&edge[ne]);
                    p1 = __ldg(&edge[ne + 1]);
                    p2 = __ldg(&edge[ne + 2]);
                    p3 = __ldg(&edge[ne + 3]);
                }
                const float4* r0 = (const float4*)(xwi + (size_t)(2 * m0.x) * FDIM);
                const float4* r1 = (const float4*)(xwi + (size_t)(2 * m1.x) * FDIM);
                const float4* r2 = (const float4*)(xwi + (size_t)(2 * m2.x) * FDIM);
                const float4* r3 = (const float4*)(xwi + (size_t)(2 * m3.x) * FDIM);
                float4 a00 = __ldg(r0 + lane);
                float4 a01 = __ldg(r0 + 32 + lane);
                float4 a10 = __ldg(r1 + lane);
                float4 a11 = __ldg(r1 + 32 + lane);
                float4 a20 = __ldg(r2 + lane);
                float4 a21 = __ldg(r2 + 32 + lane);
                float4 a30 = __ldg(r3 + lane);
                float4 a31 = __ldg(r3 + 32 + lane);
                float w0 = __uint_as_float(m0.y), w1 = __uint_as_float(m1.y);
                float w2 = __uint_as_float(m2.y), w3 = __uint_as_float(m3.y);
                acc0.x = fmaf(w0, a00.x, acc0.x); acc0.y = fmaf(w0, a00.y, acc0.y);
                acc0.z = fmaf(w0, a00.z, acc0.z); acc0.w = fmaf(w0, a00.w, acc0.w);
                acc1.x = fmaf(w0, a01.x, acc1.x); acc1.y = fmaf(w0, a01.y, acc1.y);
                acc1.z = fmaf(w0, a01.z, acc1.z); acc1.w = fmaf(w0, a01.w, acc1.w);
                acc0.x = fmaf(w1, a10.x, acc0.x); acc0.y = fmaf(w1, a10.y, acc0.y);
                acc0.z = fmaf(w1, a10.z, acc0.z); acc0.w = fmaf(w1, a10.w, acc0.w);
                acc1.x = fmaf(w1, a11.x, acc1.x); acc1.y = fmaf(w1, a11.y, acc1.y);
                acc1.z = fmaf(w1, a11.z, acc1.z); acc1.w = fmaf(w1, a11.w, acc1.w);
                acc0.x = fmaf(w2, a20.x, acc0.x); acc0.y = fmaf(w2, a20.y, acc0.y);
                acc0.z = fmaf(w2, a20.z, acc0.z); acc0.w = fmaf(w2, a20.w, acc0.w);
                acc1.x = fmaf(w2, a21.x, acc1.x); acc1.y = fmaf(w2, a21.y, acc1.y);
                acc1.z = fmaf(w2, a21.z, acc1.z); acc1.w = fmaf(w2, a21.w, acc1.w);
                acc0.x = fmaf(w3, a30.x, acc0.x); acc0.y = fmaf(w3, a30.y, acc0.y);
                acc0.z = fmaf(w3, a30.z, acc0.z); acc0.w = fmaf(w3, a30.w, acc0.w);
                acc1.x = fmaf(w3, a31.x, acc1.x); acc1.y = fmaf(w3, a31.y, acc1.y);
                acc1.z = fmaf(w3, a31.z, acc1.z); acc1.w = fmaf(w3, a31.w, acc1.w);
                m0 = p0; m1 = p1; m2 = p2; m3 = p3;
                e = ne;
            }
        }
        for (; e < en; e++) {
            uint2 m = __ldg(&edge[e]);
            const float4* r = (const float4*)(xwi + (size_t)(2 * m.x) * FDIM);
            float4 a0 = __ldg(r + lane);
            float4 a1 = __ldg(r + 32 + lane);
            float w = __uint_as_float(m.y);
            acc0.x = fmaf(w, a0.x, acc0.x); acc0.y = fmaf(w, a0.y, acc0.y);
            acc0.z = fmaf(w, a0.z, acc0.z); acc0.w = fmaf(w, a0.w, acc0.w);
            acc1.x = fmaf(w, a1.x, acc1.x); acc1.y = fmaf(w, a1.y, acc1.y);
            acc1.z = fmaf(w, a1.z, acc1.z); acc1.w = fmaf(w, a1.w, acc1.w);
        }

        float4 o0, o1;
        o0.x = fmaxf(acc0.x + bv.x, 0.f);
        o0.y = fmaxf(acc0.y + bv.y, 0.f);
        o0.z = fmaxf(acc0.z + bv.z, 0.f);
        o0.w = fmaxf(acc0.w + bv.w, 0.f);
        o1.x = fmaxf(acc1.x + bv.x, 0.f);
        o1.y = fmaxf(acc1.y + bv.y, 0.f);
        o1.z = fmaxf(acc1.z + bv.z, 0.f);
        o1.w = fmaxf(acc1.w + bv.w, 0.f);
        float4* dst = (float4*)(ti + (size_t)(2 * n) * FDIM);
        dst[lane] = o0;
        dst[32 + lane] = o1;
        s[0] += o0.x + o1.x; q[0] += o0.x * o0.x + o1.x * o1.x;
        s[1] += o0.y + o1.y; q[1] += o0.y * o0.y + o1.y * o1.y;
        s[2] += o0.z + o1.z; q[2] += o0.z * o0.z + o1.z * o1.z;
        s[3] += o0.w + o1.w; q[3] += o0.w * o0.w + o1.w * o1.w;
    }

    __shared__ float sh[256 * 8];
    #pragma unroll
    for (int j = 0; j < 4; j++) { sh[tid * 8 + j] = s[j]; sh[tid * 8 + 4 + j] = q[j]; }
    __syncthreads();
    if (tid < 32) {
        float as[4] = {0.f, 0.f, 0.f, 0.f}, aq[4] = {0.f, 0.f, 0.f, 0.f};
        for (int w = 0; w < 8; w++) {
            int src = (tid + 32 * w) * 8;
            #pragma unroll
            for (int j = 0; j < 4; j++) { as[j] += sh[src + j]; aq[j] += sh[src + 4 + j]; }
        }
        #pragma unroll
        for (int j = 0; j < 4; j++) {
            atomicAdd(&gsum[4 * tid + j], as[j]);
            atomicAdd(&gsq [4 * tid + j], aq[j]);
        }
    }
}

// ---------------- fold BN into next weight matrix ----------------------------
__global__ void k_fold(const float* __restrict__ gsum, const float* __restrict__ gsq,
                       const float* __restrict__ gamma, const float* __restrict__ beta,
                       const float* __restrict__ Wsrc, int J,
                       const float* __restrict__ extra_bias,
                       float* __restrict__ Wp, float* __restrict__ cv) {
    __shared__ float ssc[FDIM], ssh[FDIM];
    int t = threadIdx.x;  // 128
    float mu = gsum[t] * (1.0f / M_ROWS);
    float var = gsq[t] * (1.0f / M_ROWS) - mu * mu;
    float sc = gamma[t] * rsqrtf(var + EPSBN);
    ssc[t] = sc;
    ssh[t] = beta[t] - mu * sc;
    __syncthreads();
    if (t < J) {
        float acc = extra_bias ? extra_bias[t] : 0.f;
        for (int k = 0; k < FDIM; k++) {
            float w = Wsrc[k * J + t];
            Wp[k * J + t] = ssc[k] * w;
            acc += ssh[k] * w;
        }
        cv[t] = acc;
    }
}

// ---------------- classifier: out = t2 @ Wcp + bcp (un-interleaves) ----------
__global__ void k_classifier(const float* __restrict__ t2, const float* __restrict__ Wcp,
                             const float* __restrict__ bcp, float* __restrict__ out) {
    __shared__ float sWT[OUT_DIM * FDIM];  // [o][k]
    __shared__ float sb[OUT_DIM];
    int tid = threadIdx.x;  // 256
    for (int i = tid; i < FDIM * OUT_DIM; i += 256) {
        int k = i / OUT_DIM, o = i % OUT_DIM;
        sWT[o * FDIM + k] = Wcp[i];
    }
    if (tid < OUT_DIM) sb[tid] = bcp[tid];
    __syncthreads();

    int gt = blockIdx.x * blockDim.x + tid;
    int warp = gt >> 5;
    int lane = gt & 31;
    int nw = (gridDim.x * blockDim.x) >> 5;
    for (int rowJ = warp; rowJ < M_ROWS; rowJ += nw) {
        float4 v = __ldg((const float4*)(t2 + (size_t)rowJ * FDIM) + lane);
        float y[OUT_DIM];
        #pragma unroll
        for (int o = 0; o < OUT_DIM; o++) {
            float4 w = ((const float4*)(sWT + o * FDIM))[lane];
            y[o] = v.x * w.x + v.y * w.y + v.z * w.z + v.w * w.w;
        }
        #pragma unroll
        for (int off = 16; off; off >>= 1)
            #pragma unroll
            for (int o = 0; o < OUT_DIM; o++)
                y[o] += __shfl_xor_sync(0xffffffffu, y[o], off);
        if (lane < OUT_DIM) {
            int n = rowJ >> 1, b = rowJ & 1;
            out[(size_t)(b * N_NODES + n) * OUT_DIM + lane] = y[lane] + sb[lane];
        }
    }
}

// ---------------- launch -----------------------------------------------------
extern "C" void kernel_launch(void* const* d_in, const int* in_sizes, int n_in,
                              void* d_out, int out_size) {
    const float* x   = (const float*)d_in[0];
    const int*   ei  = (const int*)d_in[1];
    const float* ewp = (const float*)d_in[2];
    const float* W1  = (const float*)d_in[3];
    const float* b1  = (const float*)d_in[4];
    const float* W2  = (const float*)d_in[5];
    const float* b2  = (const float*)d_in[6];
    const float* g1  = (const float*)d_in[7];
    const float* be1 = (const float*)d_in[8];
    const float* g2  = (const float*)d_in[9];
    const float* be2 = (const float*)d_in[10];
    const float* Wc  = (const float*)d_in[11];
    const float* bc  = (const float*)d_in[12];
    float* out = (float*)d_out;
    const int* row = ei;
    const int* col = ei + N_EDGES;

    float *p_xw, *p_t, *p_dinv, *p_deg;
    float *p_W2p, *p_cvec, *p_Wcp, *p_bcp, *p_sum, *p_sq;
    int *p_cnt, *p_start, *p_cursor, *p_partial, *p_pscan;
    uint2* p_edge;
    cudaGetSymbolAddress((void**)&p_xw,   g_xw);
    cudaGetSymbolAddress((void**)&p_t,    g_t);
    cudaGetSymbolAddress((void**)&p_dinv, g_dinv);
    cudaGetSymbolAddress((void**)&p_deg,  g_deg);
    cudaGetSymbolAddress((void**)&p_cnt,  g_cnt);
    cudaGetSymbolAddress((void**)&p_start, g_start);
    cudaGetSymbolAddress((void**)&p_cursor, g_cursor);
    cudaGetSymbolAddress((void**)&p_partial, g_partial);
    cudaGetSymbolAddress((void**)&p_pscan, g_pscan);
    cudaGetSymbolAddress((void**)&p_edge, g_edge);
    cudaGetSymbolAddress((void**)&p_W2p,  g_W2p);
    cudaGetSymbolAddress((void**)&p_cvec, g_cvec);
    cudaGetSymbolAddress((void**)&p_Wcp,  g_Wcp);
    cudaGetSymbolAddress((void**)&p_bcp,  g_bcp);
    cudaGetSymbolAddress((void**)&p_sum,  g_sum);
    cudaGetSymbolAddress((void**)&p_sq,   g_sq);

    (void)cudaFuncSetAttribute(k_gemm128, cudaFuncAttributeMaxDynamicSharedMemorySize, 98304);

    // --- CSR build + layer-1 GEMM, ordered so ncu (-s 5 -c 1) profiles the GEMM
    k_init      <<<(N_NODES + 255) / 256, 256>>>(p_deg, p_cnt);                     // 1
    k_pass1     <<<(N_EDGES + 255) / 256, 256>>>(ewp, col, p_deg, p_cnt);           // 2
    k_dinv      <<<(N_NODES + 255) / 256, 256>>>(p_deg, p_dinv);                    // 3
    k_scan1     <<<NBLK_SCAN, 256>>>(p_cnt, p_partial);                             // 4
    k_scan2     <<<1, 256>>>(p_partial, p_pscan, p_start);                          // 5
    k_gemm128   <<<592, 256, 98304>>>(x, W1, nullptr, p_xw, M_ROWS, 1);             // 6 <- ncu
    k_scan3     <<<NBLK_SCAN, 256>>>(p_cnt, p_pscan, p_start, p_cursor);            // 7
    k_sortedges <<<(N_EDGES + 255) / 256, 256>>>(ewp, row, col, p_dinv, p_cursor, p_edge);

    // --- layer 1 aggregation (both batches in one pass) ---
    cudaMemsetAsync(p_sum, 0, FDIM * sizeof(float), 0);
    cudaMemsetAsync(p_sq,  0, FDIM * sizeof(float), 0);
    k_agg<<<1184, 256>>>(p_xw, p_edge, p_start, p_dinv, b1, p_t, p_sum, p_sq);
    k_fold<<<1, 128>>>(p_sum, p_sq, g1, be1, W2, FDIM, nullptr, p_W2p, p_cvec);

    // --- layer 2 (BN1 folded into W2; t already interleaved -> no remap) ---
    k_gemm128<<<592, 256, 98304>>>(p_t, p_W2p, p_cvec, p_xw, M_ROWS, 0);
    cudaMemsetAsync(p_sum, 0, FDIM * sizeof(float), 0);
    cudaMemsetAsync(p_sq,  0, FDIM * sizeof(float), 0);
    k_agg<<<1184, 256>>>(p_xw, p_edge, p_start, p_dinv, b2, p_t, p_sum, p_sq);
    k_fold<<<1, 128>>>(p_sum, p_sq, g2, be2, Wc, OUT_DIM, bc, p_Wcp, p_bcp);

    // --- classifier (BN2 folded into Wc; un-interleaves on store) ---
    k_classifier<<<1024, 256>>>(p_t, p_Wcp, p_bcp, out);
}

// round 9
// speedup vs baseline: 1.8212x; 1.0403x over previous
#include <cuda_runtime.h>
#include <cuda_fp16.h>

#define N_NODES 50000
#define N_EDGES 640000
#define FDIM    128
#define OUT_DIM 16
#define BATCH   2
#define M_ROWS  (BATCH * N_NODES)   /* 100000 flattened rows */
#define EPSBN   1e-5f
#define NBLK_SCAN ((N_NODES + 255) / 256)   /* 196 */

// ---------------- scratch (device globals; no allocation allowed) -------------
__device__ __align__(128) __half g_xw [(size_t)M_ROWS * FDIM];  // GEMM outputs, fp16, interleaved [n][b][128]
__device__ __align__(128) float g_t   [(size_t)M_ROWS * FDIM];  // relu(conv) activations (fp32, interleaved)
__device__ __align__(128) float g_dinv[N_NODES];
__device__ __align__(128) float g_deg [N_NODES];
__device__ __align__(128) int   g_cnt   [N_NODES];
__device__ __align__(128) int   g_start [N_NODES + 1];
__device__ __align__(128) int   g_cursor[N_NODES];
__device__ __align__(128) int   g_partial[256];
__device__ __align__(128) int   g_pscan  [256];
__device__ __align__(128) uint2 g_edge  [N_EDGES];              // {src, norm-bits} sorted by dst
__device__ __align__(128) float g_W2p [FDIM * FDIM];
__device__ __align__(128) float g_cvec[FDIM];
__device__ __align__(128) float g_Wcp [FDIM * OUT_DIM];
__device__ __align__(128) float g_bcp [OUT_DIM];
__device__ __align__(128) float g_sum [FDIM];
__device__ __align__(128) float g_sq  [FDIM];

// ---------------- init: deg=1 (self loop), cnt=0 ----------------------------
__global__ void k_init(float* deg, int* cnt) {
    int i = blockIdx.x * blockDim.x + threadIdx.x;
    if (i < N_NODES) { deg[i] = 1.0f; cnt[i] = 0; }
}

// ---------------- pass1: degree accumulation + dst histogram -----------------
__global__ void k_pass1(const float* __restrict__ ewp, const int* __restrict__ col,
                        float* deg, int* cnt) {
    int e = blockIdx.x * blockDim.x + threadIdx.x;
    if (e < N_EDGES) {
        int c = col[e];
        atomicAdd(&deg[c], expf(ewp[e]));
        atomicAdd(&cnt[c], 1);
    }
}

__global__ void k_dinv(const float* __restrict__ deg, float* dinv) {
    int i = blockIdx.x * blockDim.x + threadIdx.x;
    if (i < N_NODES) {
        float d = deg[i];
        dinv[i] = (d > 0.f) ? rsqrtf(d) : 0.f;
    }
}

// ---------------- hierarchical scan (3 kernels, all coalesced) ---------------
__global__ void k_scan1(const int* __restrict__ cnt, int* __restrict__ partial) {
    __shared__ int sh[8];
    int idx = blockIdx.x * 256 + threadIdx.x;
    int v = (idx < N_NODES) ? cnt[idx] : 0;
    #pragma unroll
    for (int off = 16; off; off >>= 1) v += __shfl_down_sync(0xffffffffu, v, off);
    if ((threadIdx.x & 31) == 0) sh[threadIdx.x >> 5] = v;
    __syncthreads();
    if (threadIdx.x == 0) {
        int s = 0;
        #pragma unroll
        for (int w = 0; w < 8; w++) s += sh[w];
        partial[blockIdx.x] = s;
    }
}

__global__ void k_scan2(const int* __restrict__ partial, int* __restrict__ pscan,
                        int* __restrict__ start) {
    __shared__ int sh[256];
    int t = threadIdx.x;
    int v = (t < NBLK_SCAN) ? partial[t] : 0;
    sh[t] = v;
    __syncthreads();
    #pragma unroll
    for (int off = 1; off < 256; off <<= 1) {
        int u = (t >= off) ? sh[t - off] : 0;
        __syncthreads();
        sh[t] += u;
        __syncthreads();
    }
    if (t < NBLK_SCAN) pscan[t] = sh[t] - v;   // exclusive
    if (t == 0) start[N_NODES] = N_EDGES;
}

__global__ void k_scan3(const int* __restrict__ cnt, const int* __restrict__ pscan,
                        int* __restrict__ start, int* __restrict__ cursor) {
    __shared__ int sh[256];
    int t = threadIdx.x;
    int idx = blockIdx.x * 256 + t;
    int v = (idx < N_NODES) ? cnt[idx] : 0;
    sh[t] = v;
    __syncthreads();
    #pragma unroll
    for (int off = 1; off < 256; off <<= 1) {
        int u = (t >= off) ? sh[t - off] : 0;
        __syncthreads();
        sh[t] += u;
        __syncthreads();
    }
    if (idx < N_NODES) {
        int excl = sh[t] - v + pscan[blockIdx.x];
        start[idx] = excl;
        cursor[idx] = excl;
    }
}

// ---------------- bucket scatter: sorted {src, norm} per destination ---------
__global__ void k_sortedges(const float* __restrict__ ewp, const int* __restrict__ row,
                            const int* __restrict__ col, const float* __restrict__ dinv,
                            int* cursor, uint2* __restrict__ edge) {
    int e = blockIdx.x * blockDim.x + threadIdx.x;
    if (e < N_EDGES) {
        int r = row[e];
        int c = col[e];
        float nm = dinv[r] * expf(ewp[e]) * dinv[c];
        int pos = atomicAdd(&cursor[c], 1);
        edge[pos] = make_uint2((unsigned)r, __float_as_uint(nm));
    }
}

// ---------------- GEMM: C_half[M x128] = A[M x128] @ W[128x128] (+ cvec) -----
// fp32 inputs / f32x2 accumulation, fp16 output.
// remap!=0: output row j corresponds to input row (j&1)*N_NODES + (j>>1)
__global__ __launch_bounds__(256) void k_gemm128(const float* __restrict__ A,
                                                 const float* __restrict__ W,
                                                 const float* __restrict__ cvec,
                                                 __half* __restrict__ C, int Mrows,
                                                 int remap) {
    extern __shared__ float smem[];
    float* sW = smem;            // 128*128 floats = 64 KB
    float* sA = smem + 16384;    // 64*128 floats = 32 KB
    const int tid = threadIdx.x;

    {   // load W once per block
        const float4* W4 = (const float4*)W;
        float4* sW4 = (float4*)sW;
        #pragma unroll
        for (int i = 0; i < 16; i++) sW4[tid + i * 256] = W4[tid + i * 256];
    }

    const int tc = tid & 15;   // cols 8*tc .. 8*tc+7
    const int tr = tid >> 4;   // rows 4*tr .. 4*tr+3

    unsigned long long initc[4];
    if (cvec) {
        #pragma unroll
        for (int p = 0; p < 4; p++) {
            float2 cv2 = *(const float2*)(cvec + 8 * tc + 2 * p);
            asm("mov.b64 %0, {%1, %2};" : "=l"(initc[p]) : "f"(cv2.x), "f"(cv2.y));
        }
    } else {
        #pragma unroll
        for (int p = 0; p < 4; p++) initc[p] = 0ull;
    }

    const int ntiles = (Mrows + 63) >> 6;
    for (int tile = blockIdx.x; tile < ntiles; tile += gridDim.x) {
        const int base = tile << 6;
        __syncthreads();
        #pragma unroll
        for (int i = 0; i < 8; i++) {
            int f4 = tid + i * 256;
            int r = f4 >> 5;
            int c4 = f4 & 31;
            int grow = base + r;
            float4 v = make_float4(0.f, 0.f, 0.f, 0.f);
            if (grow < Mrows) {
                int irow = remap ? ((grow & 1) * N_NODES + (grow >> 1)) : grow;
                v = ((const float4*)A)[(size_t)irow * 32 + c4];
            }
            ((float4*)sA)[f4] = v;
        }
        __syncthreads();

        unsigned long long acc[4][4];
        #pragma unroll
        for (int r = 0; r < 4; r++)
            #pragma unroll
            for (int p = 0; p < 4; p++) acc[r][p] = initc[p];

        const float* aBase = sA + (tr << 2) * FDIM;
        #pragma unroll 2
        for (int k0 = 0; k0 < FDIM; k0 += 4) {
            float4 a0 = *(const float4*)(aBase + k0);
            float4 a1 = *(const float4*)(aBase + FDIM + k0);
            float4 a2 = *(const float4*)(aBase + 2 * FDIM + k0);
            float4 a3 = *(const float4*)(aBase + 3 * FDIM + k0);
            float am[4][4] = {{a0.x, a0.y, a0.z, a0.w}, {a1.x, a1.y, a1.z, a1.w},
                              {a2.x, a2.y, a2.z, a2.w}, {a3.x, a3.y, a3.z, a3.w}};
            #pragma unroll
            for (int kk = 0; kk < 4; kk++) {
                const ulonglong2* bp = (const ulonglong2*)(sW + (k0 + kk) * FDIM + (tc << 3));
                ulonglong2 b01 = bp[0];
                ulonglong2 b23 = bp[1];
                unsigned long long bv[4] = {b01.x, b01.y, b23.x, b23.y};
                unsigned long long pa[4];
                #pragma unroll
                for (int r = 0; r < 4; r++)
                    asm("mov.b64 %0, {%1, %1};" : "=l"(pa[r]) : "f"(am[r][kk]));
                #pragma unroll
                for (int r = 0; r < 4; r++)
                    #pragma unroll
                    for (int p = 0; p < 4; p++)
                        asm("fma.rn.f32x2 %0, %1, %2, %0;"
                            : "+l"(acc[r][p]) : "l"(pa[r]), "l"(bv[p]));
            }
        }

        #pragma unroll
        for (int r = 0; r < 4; r++) {
            int grow = base + (tr << 2) + r;
            if (grow < Mrows) {
                uint4 st;
                unsigned hh[4];
                #pragma unroll
                for (int p = 0; p < 4; p++) {
                    float lo, hi;
                    asm("mov.b64 {%0, %1}, %2;" : "=f"(lo), "=f"(hi) : "l"(acc[r][p]));
                    __half2 h = __floats2half2_rn(lo, hi);
                    hh[p] = *(unsigned*)&h;
                }
                st.x = hh[0]; st.y = hh[1]; st.z = hh[2]; st.w = hh[3];
                *(uint4*)(C + (size_t)grow * FDIM + (tc << 3)) = st;
            }
        }
    }
}

// ---------------- fused aggregate (BOTH batches) + self + bias + relu + BN ---
// fp16 interleaved xw [n][b][128]: warp per node, edge meta read once, each
// edge gathers one contiguous 512B block (both batch rows, fp16).
__device__ __forceinline__ float4 h4f(uint2 u) {
    __half2 a = *(__half2*)&u.x;
    __half2 b = *(__half2*)&u.y;
    float2 fa = __half22float2(a);
    float2 fb = __half22float2(b);
    return make_float4(fa.x, fa.y, fb.x, fb.y);
}

__global__ __launch_bounds__(256) void k_agg(const __half* __restrict__ xwi,
                                             const uint2* __restrict__ edge,
                                             const int* __restrict__ start,
                                             const float* __restrict__ dinv,
                                             const float* __restrict__ bias,
                                             float* __restrict__ ti,
                                             float* __restrict__ gsum,
                                             float* __restrict__ gsq) {
    const int tid = threadIdx.x;
    const int lane = tid & 31;
    const int gw = (blockIdx.x * blockDim.x + tid) >> 5;
    const int nwarps = (gridDim.x * blockDim.x) >> 5;
    const float4 bv = ((const float4*)bias)[lane];
    float s[4] = {0.f, 0.f, 0.f, 0.f}, q[4] = {0.f, 0.f, 0.f, 0.f};

    for (int n = gw; n < N_NODES; n += nwarps) {
        const int st = start[n];
        const int en = start[n + 1];
        const float d = dinv[n];
        const float d2 = d * d;
        const uint2* self = (const uint2*)(xwi + (size_t)(2 * n) * FDIM);
        float4 v0 = h4f(__ldg(self + lane));
        float4 v1 = h4f(__ldg(self + 32 + lane));
        float4 acc0 = make_float4(d2 * v0.x, d2 * v0.y, d2 * v0.z, d2 * v0.w);
        float4 acc1 = make_float4(d2 * v1.x, d2 * v1.y, d2 * v1.z, d2 * v1.w);

        const int cnt4 = (en - st) >> 2;
        int e = st;
        if (cnt4 > 0) {
            uint2 m0 = __ldg(&edge[e]);
            uint2 m1 = __ldg(&edge[e + 1]);
            uint2 m2 = __ldg(&edge[e + 2]);
            uint2 m3 = __ldg(&edge[e + 3]);
            for (int g = 0; g < cnt4; g++) {
                uint2 p0, p1, p2, p3;
                const int ne = e + 4;
                if (g + 1 < cnt4) {             // prefetch next group's metadata
                    p0 = __ldg(&edge[ne]);
                    p1 = __ldg(&edge[ne + 1]);
                    p2 = __ldg(&edge[ne + 2]);
                    p3 = __ldg(&edge[ne + 3]);
                }
                const uint2* r0 = (const uint2*)(xwi + (size_t)(2 * m0.x) * FDIM);
                const uint2* r1 = (const uint2*)(xwi + (size_t)(2 * m1.x) * FDIM);
                const uint2* r2 = (const uint2*)(xwi + (size_t)(2 * m2.x) * FDIM);
                const uint2* r3 = (const uint2*)(xwi + (size_t)(2 * m3.x) * FDIM);
                float4 a00 = h4f(__ldg(r0 + lane));
                float4 a01 = h4f(__ldg(r0 + 32 + lane));
                float4 a10 = h4f(__ldg(r1 + lane));
                float4 a11 = h4f(__ldg(r1 + 32 + lane));
                float4 a20 = h4f(__ldg(r2 + lane));
                float4 a21 = h4f(__ldg(r2 + 32 + lane));
                float4 a30 = h4f(__ldg(r3 + lane));
                float4 a31 = h4f(__ldg(r3 + 32 + lane));
                float w0 = __uint_as_float(m0.y), w1 = __uint_as_float(m1.y);
                float w2 = __uint_as_float(m2.y), w3 = __uint_as_float(m3.y);
                acc0.x = fmaf(w0, a00.x, acc0.x); acc0.y = fmaf(w0, a00.y, acc0.y);
                acc0.z = fmaf(w0, a00.z, acc0.z); acc0.w = fmaf(w0, a00.w, acc0.w);
                acc1.x = fmaf(w0, a01.x, acc1.x); acc1.y = fmaf(w0, a01.y, acc1.y);
                acc1.z = fmaf(w0, a01.z, acc1.z); acc1.w = fmaf(w0, a01.w, acc1.w);
                acc0.x = fmaf(w1, a10.x, acc0.x); acc0.y = fmaf(w1, a10.y, acc0.y);
                acc0.z = fmaf(w1, a10.z, acc0.z); acc0.w = fmaf(w1, a10.w, acc0.w);
                acc1.x = fmaf(w1, a11.x, acc1.x); acc1.y = fmaf(w1, a11.y, acc1.y);
                acc1.z = fmaf(w1, a11.z, acc1.z); acc1.w = fmaf(w1, a11.w, acc1.w);
                acc0.x = fmaf(w2, a20.x, acc0.x); acc0.y = fmaf(w2, a20.y, acc0.y);
                acc0.z = fmaf(w2, a20.z, acc0.z); acc0.w = fmaf(w2, a20.w, acc0.w);
                acc1.x = fmaf(w2, a21.x, acc1.x); acc1.y = fmaf(w2, a21.y, acc1.y);
                acc1.z = fmaf(w2, a21.z, acc1.z); acc1.w = fmaf(w2, a21.w, acc1.w);
                acc0.x = fmaf(w3, a30.x, acc0.x); acc0.y = fmaf(w3, a30.y, acc0.y);
                acc0.z = fmaf(w3, a30.z, acc0.z); acc0.w = fmaf(w3, a30.w, acc0.w);
                acc1.x = fmaf(w3, a31.x, acc1.x); acc1.y = fmaf(w3, a31.y, acc1.y);
                acc1.z = fmaf(w3, a31.z, acc1.z); acc1.w = fmaf(w3, a31.w, acc1.w);
                m0 = p0; m1 = p1; m2 = p2; m3 = p3;
                e = ne;
            }
        }
        for (; e < en; e++) {
            uint2 m = __ldg(&edge[e]);
            const uint2* r = (const uint2*)(xwi + (size_t)(2 * m.x) * FDIM);
            float4 a0 = h4f(__ldg(r + lane));
            float4 a1 = h4f(__ldg(r + 32 + lane));
            float w = __uint_as_float(m.y);
            acc0.x = fmaf(w, a0.x, acc0.x); acc0.y = fmaf(w, a0.y, acc0.y);
            acc0.z = fmaf(w, a0.z, acc0.z); acc0.w = fmaf(w, a0.w, acc0.w);
            acc1.x = fmaf(w, a1.x, acc1.x); acc1.y = fmaf(w, a1.y, acc1.y);
            acc1.z = fmaf(w, a1.z, acc1.z); acc1.w = fmaf(w, a1.w, acc1.w);
        }

        float4 o0, o1;
        o0.x = fmaxf(acc0.x + bv.x, 0.f);
        o0.y = fmaxf(acc0.y + bv.y, 0.f);
        o0.z = fmaxf(acc0.z + bv.z, 0.f);
        o0.w = fmaxf(acc0.w + bv.w, 0.f);
        o1.x = fmaxf(acc1.x + bv.x, 0.f);
        o1.y = fmaxf(acc1.y + bv.y, 0.f);
        o1.z = fmaxf(acc1.z + bv.z, 0.f);
        o1.w = fmaxf(acc1.w + bv.w, 0.f);
        float4* dst = (float4*)(ti + (size_t)(2 * n) * FDIM);
        dst[lane] = o0;
        dst[32 + lane] = o1;
        s[0] += o0.x + o1.x; q[0] += o0.x * o0.x + o1.x * o1.x;
        s[1] += o0.y + o1.y; q[1] += o0.y * o0.y + o1.y * o1.y;
        s[2] += o0.z + o1.z; q[2] += o0.z * o0.z + o1.z * o1.z;
        s[3] += o0.w + o1.w; q[3] += o0.w * o0.w + o1.w * o1.w;
    }

    __shared__ float sh[256 * 8];
    #pragma unroll
    for (int j = 0; j < 4; j++) { sh[tid * 8 + j] = s[j]; sh[tid * 8 + 4 + j] = q[j]; }
    __syncthreads();
    if (tid < 32) {
        float as[4] = {0.f, 0.f, 0.f, 0.f}, aq[4] = {0.f, 0.f, 0.f, 0.f};
        for (int w = 0; w < 8; w++) {
            int src = (tid + 32 * w) * 8;
            #pragma unroll
            for (int j = 0; j < 4; j++) { as[j] += sh[src + j]; aq[j] += sh[src + 4 + j]; }
        }
        #pragma unroll
        for (int j = 0; j < 4; j++) {
            atomicAdd(&gsum[4 * tid + j], as[j]);
            atomicAdd(&gsq [4 * tid + j], aq[j]);
        }
    }
}

// ---------------- fold BN into next weight matrix ----------------------------
__global__ void k_fold(const float* __restrict__ gsum, const float* __restrict__ gsq,
                       const float* __restrict__ gamma, const float* __restrict__ beta,
                       const float* __restrict__ Wsrc, int J,
                       const float* __restrict__ extra_bias,
                       float* __restrict__ Wp, float* __restrict__ cv) {
    __shared__ float ssc[FDIM], ssh[FDIM];
    int t = threadIdx.x;  // 128
    float mu = gsum[t] * (1.0f / M_ROWS);
    float var = gsq[t] * (1.0f / M_ROWS) - mu * mu;
    float sc = gamma[t] * rsqrtf(var + EPSBN);
    ssc[t] = sc;
    ssh[t] = beta[t] - mu * sc;
    __syncthreads();
    if (t < J) {
        float acc = extra_bias ? extra_bias[t] : 0.f;
        for (int k = 0; k < FDIM; k++) {
            float w = Wsrc[k * J + t];
            Wp[k * J + t] = ssc[k] * w;
            acc += ssh[k] * w;
        }
        cv[t] = acc;
    }
}

// ---------------- classifier: out = t2 @ Wcp + bcp (un-interleaves) ----------
__global__ void k_classifier(const float* __restrict__ t2, const float* __restrict__ Wcp,
                             const float* __restrict__ bcp, float* __restrict__ out) {
    __shared__ float sWT[OUT_DIM * FDIM];  // [o][k]
    __shared__ float sb[OUT_DIM];
    int tid = threadIdx.x;  // 256
    for (int i = tid; i < FDIM * OUT_DIM; i += 256) {
        int k = i / OUT_DIM, o = i % OUT_DIM;
        sWT[o * FDIM + k] = Wcp[i];
    }
    if (tid < OUT_DIM) sb[tid] = bcp[tid];
    __syncthreads();

    int gt = blockIdx.x * blockDim.x + tid;
    int warp = gt >> 5;
    int lane = gt & 31;
    int nw = (gridDim.x * blockDim.x) >> 5;
    for (int rowJ = warp; rowJ < M_ROWS; rowJ += nw) {
        float4 v = __ldg((const float4*)(t2 + (size_t)rowJ * FDIM) + lane);
        float y[OUT_DIM];
        #pragma unroll
        for (int o = 0; o < OUT_DIM; o++) {
            float4 w = ((const float4*)(sWT + o * FDIM))[lane];
            y[o] = v.x * w.x + v.y * w.y + v.z * w.z + v.w * w.w;
        }
        #pragma unroll
        for (int off = 16; off; off >>= 1)
            #pragma unroll
            for (int o = 0; o < OUT_DIM; o++)
                y[o] += __shfl_xor_sync(0xffffffffu, y[o], off);
        if (lane < OUT_DIM) {
            int n = rowJ >> 1, b = rowJ & 1;
            out[(size_t)(b * N_NODES + n) * OUT_DIM + lane] = y[lane] + sb[lane];
        }
    }
}

// ---------------- launch -----------------------------------------------------
extern "C" void kernel_launch(void* const* d_in, const int* in_sizes, int n_in,
                              void* d_out, int out_size) {
    const float* x   = (const float*)d_in[0];
    const int*   ei  = (const int*)d_in[1];
    const float* ewp = (const float*)d_in[2];
    const float* W1  = (const float*)d_in[3];
    const float* b1  = (const float*)d_in[4];
    const float* W2  = (const float*)d_in[5];
    const float* b2  = (const float*)d_in[6];
    const float* g1  = (const float*)d_in[7];
    const float* be1 = (const float*)d_in[8];
    const float* g2  = (const float*)d_in[9];
    const float* be2 = (const float*)d_in[10];
    const float* Wc  = (const float*)d_in[11];
    const float* bc  = (const float*)d_in[12];
    float* out = (float*)d_out;
    const int* row = ei;
    const int* col = ei + N_EDGES;

    float *p_t, *p_dinv, *p_deg;
    float *p_W2p, *p_cvec, *p_Wcp, *p_bcp, *p_sum, *p_sq;
    int *p_cnt, *p_start, *p_cursor, *p_partial, *p_pscan;
    uint2* p_edge;
    __half* p_xw;
    cudaGetSymbolAddress((void**)&p_xw,   g_xw);
    cudaGetSymbolAddress((void**)&p_t,    g_t);
    cudaGetSymbolAddress((void**)&p_dinv, g_dinv);
    cudaGetSymbolAddress((void**)&p_deg,  g_deg);
    cudaGetSymbolAddress((void**)&p_cnt,  g_cnt);
    cudaGetSymbolAddress((void**)&p_start, g_start);
    cudaGetSymbolAddress((void**)&p_cursor, g_cursor);
    cudaGetSymbolAddress((void**)&p_partial, g_partial);
    cudaGetSymbolAddress((void**)&p_pscan, g_pscan);
    cudaGetSymbolAddress((void**)&p_edge, g_edge);
    cudaGetSymbolAddress((void**)&p_W2p,  g_W2p);
    cudaGetSymbolAddress((void**)&p_cvec, g_cvec);
    cudaGetSymbolAddress((void**)&p_Wcp,  g_Wcp);
    cudaGetSymbolAddress((void**)&p_bcp,  g_bcp);
    cudaGetSymbolAddress((void**)&p_sum,  g_sum);
    cudaGetSymbolAddress((void**)&p_sq,   g_sq);

    (void)cudaFuncSetAttribute(k_gemm128, cudaFuncAttributeMaxDynamicSharedMemorySize, 98304);

    // --- CSR build + layer-1 GEMM ---
    k_init      <<<(N_NODES + 255) / 256, 256>>>(p_deg, p_cnt);
    k_pass1     <<<(N_EDGES + 255) / 256, 256>>>(ewp, col, p_deg, p_cnt);
    k_dinv      <<<(N_NODES + 255) / 256, 256>>>(p_deg, p_dinv);
    k_scan1     <<<NBLK_SCAN, 256>>>(p_cnt, p_partial);
    k_scan2     <<<1, 256>>>(p_partial, p_pscan, p_start);
    k_gemm128   <<<592, 256, 98304>>>(x, W1, nullptr, p_xw, M_ROWS, 1);
    k_scan3     <<<NBLK_SCAN, 256>>>(p_cnt, p_pscan, p_start, p_cursor);
    k_sortedges <<<(N_EDGES + 255) / 256, 256>>>(ewp, row, col, p_dinv, p_cursor, p_edge);

    // --- layer 1 aggregation (both batches in one pass) ---
    cudaMemsetAsync(p_sum, 0, FDIM * sizeof(float), 0);
    cudaMemsetAsync(p_sq,  0, FDIM * sizeof(float), 0);
    k_agg<<<1184, 256>>>(p_xw, p_edge, p_start, p_dinv, b1, p_t, p_sum, p_sq);
    k_fold<<<1, 128>>>(p_sum, p_sq, g1, be1, W2, FDIM, nullptr, p_W2p, p_cvec);

    // --- layer 2 (BN1 folded into W2; t interleaved fp32 -> no remap) ---
    k_gemm128<<<592, 256, 98304>>>(p_t, p_W2p, p_cvec, p_xw, M_ROWS, 0);
    cudaMemsetAsync(p_sum, 0, FDIM * sizeof(float), 0);
    cudaMemsetAsync(p_sq,  0, FDIM * sizeof(float), 0);
    k_agg<<<1184, 256>>>(p_xw, p_edge, p_start, p_dinv, b2, p_t, p_sum, p_sq);
    k_fold<<<1, 128>>>(p_sum, p_sq, g2, be2, Wc, OUT_DIM, bc, p_Wcp, p_bcp);

    // --- classifier (BN2 folded into Wc; un-interleaves on store) ---
    k_classifier<<<1024, 256>>>(p_t, p_Wcp, p_bcp, out);
}

// round 11
// speedup vs baseline: 1.9493x; 1.0703x over previous
#include <cuda_runtime.h>
#include <cuda_fp16.h>

#define N_NODES 50000
#define N_EDGES 640000
#define FDIM    128
#define OUT_DIM 16
#define BATCH   2
#define M_ROWS  (BATCH * N_NODES)   /* 100000 flattened rows */
#define EPSBN   1e-5f
#define NBLK_SCAN ((N_NODES + 255) / 256)   /* 196 */

// ---------------- scratch (device globals; no allocation allowed) -------------
__device__ __align__(128) __half g_xw [(size_t)M_ROWS * FDIM];  // GEMM outputs, fp16, interleaved [n][b][128]
__device__ __align__(128) float g_t   [(size_t)M_ROWS * FDIM];  // relu(conv) activations (fp32, interleaved)
__device__ __align__(128) float g_dinv[N_NODES];
__device__ __align__(128) float g_deg [N_NODES];
__device__ __align__(128) int   g_cnt   [N_NODES];
__device__ __align__(128) int   g_start [N_NODES + 1];
__device__ __align__(128) int   g_cursor[N_NODES];
__device__ __align__(128) int   g_partial[256];
__device__ __align__(128) int   g_pscan  [256];
__device__ __align__(128) uint2 g_edge  [N_EDGES];              // {src, norm-bits} sorted by dst
__device__ __align__(128) float g_W2p [FDIM * FDIM];
__device__ __align__(128) float g_cvec[FDIM];
__device__ __align__(128) float g_Wcp [FDIM * OUT_DIM];
__device__ __align__(128) float g_bcp [OUT_DIM];
__device__ __align__(128) float g_sum [FDIM];
__device__ __align__(128) float g_sq  [FDIM];

// ---------------- init: deg=1 (self loop), cnt=0 ----------------------------
__global__ void k_init(float* deg, int* cnt) {
    int i = blockIdx.x * blockDim.x + threadIdx.x;
    if (i < N_NODES) { deg[i] = 1.0f; cnt[i] = 0; }
}

// ---------------- pass1: degree accumulation + dst histogram -----------------
__global__ void k_pass1(const float* __restrict__ ewp, const int* __restrict__ col,
                        float* deg, int* cnt) {
    int e = blockIdx.x * blockDim.x + threadIdx.x;
    if (e < N_EDGES) {
        int c = col[e];
        atomicAdd(&deg[c], expf(ewp[e]));
        atomicAdd(&cnt[c], 1);
    }
}

__global__ void k_dinv(const float* __restrict__ deg, float* dinv) {
    int i = blockIdx.x * blockDim.x + threadIdx.x;
    if (i < N_NODES) {
        float d = deg[i];
        dinv[i] = (d > 0.f) ? rsqrtf(d) : 0.f;
    }
}

// ---------------- hierarchical scan (3 kernels, all coalesced) ---------------
__global__ void k_scan1(const int* __restrict__ cnt, int* __restrict__ partial) {
    __shared__ int sh[8];
    int idx = blockIdx.x * 256 + threadIdx.x;
    int v = (idx < N_NODES) ? cnt[idx] : 0;
    #pragma unroll
    for (int off = 16; off; off >>= 1) v += __shfl_down_sync(0xffffffffu, v, off);
    if ((threadIdx.x & 31) == 0) sh[threadIdx.x >> 5] = v;
    __syncthreads();
    if (threadIdx.x == 0) {
        int s = 0;
        #pragma unroll
        for (int w = 0; w < 8; w++) s += sh[w];
        partial[blockIdx.x] = s;
    }
}

__global__ void k_scan2(const int* __restrict__ partial, int* __restrict__ pscan,
                        int* __restrict__ start) {
    __shared__ int sh[256];
    int t = threadIdx.x;
    int v = (t < NBLK_SCAN) ? partial[t] : 0;
    sh[t] = v;
    __syncthreads();
    #pragma unroll
    for (int off = 1; off < 256; off <<= 1) {
        int u = (t >= off) ? sh[t - off] : 0;
        __syncthreads();
        sh[t] += u;
        __syncthreads();
    }
    if (t < NBLK_SCAN) pscan[t] = sh[t] - v;   // exclusive
    if (t == 0) start[N_NODES] = N_EDGES;
}

__global__ void k_scan3(const int* __restrict__ cnt, const int* __restrict__ pscan,
                        int* __restrict__ start, int* __restrict__ cursor) {
    __shared__ int sh[256];
    int t = threadIdx.x;
    int idx = blockIdx.x * 256 + t;
    int v = (idx < N_NODES) ? cnt[idx] : 0;
    sh[t] = v;
    __syncthreads();
    #pragma unroll
    for (int off = 1; off < 256; off <<= 1) {
        int u = (t >= off) ? sh[t - off] : 0;
        __syncthreads();
        sh[t] += u;
        __syncthreads();
    }
    if (idx < N_NODES) {
        int excl = sh[t] - v + pscan[blockIdx.x];
        start[idx] = excl;
        cursor[idx] = excl;
    }
}

// ---------------- bucket scatter: sorted {src, norm} per destination ---------
__global__ void k_sortedges(const float* __restrict__ ewp, const int* __restrict__ row,
                            const int* __restrict__ col, const float* __restrict__ dinv,
                            int* cursor, uint2* __restrict__ edge) {
    int e = blockIdx.x * blockDim.x + threadIdx.x;
    if (e < N_EDGES) {
        int r = row[e];
        int c = col[e];
        float nm = dinv[r] * expf(ewp[e]) * dinv[c];
        int pos = atomicAdd(&cursor[c], 1);
        edge[pos] = make_uint2((unsigned)r, __float_as_uint(nm));
    }
}

// ---------------- GEMM: C_half[M x128] = A[M x128] @ W[128x128] (+ cvec) -----
// fp32 inputs / f32x2 accumulation, fp16 output.
// remap!=0: output row j corresponds to input row (j&1)*N_NODES + (j>>1)
__global__ __launch_bounds__(256) void k_gemm128(const float* __restrict__ A,
                                                 const float* __restrict__ W,
                                                 const float* __restrict__ cvec,
                                                 __half* __restrict__ C, int Mrows,
                                                 int remap) {
    extern __shared__ float smem[];
    float* sW = smem;            // 128*128 floats = 64 KB
    float* sA = smem + 16384;    // 64*128 floats = 32 KB
    const int tid = threadIdx.x;

    {   // load W once per block
        const float4* W4 = (const float4*)W;
        float4* sW4 = (float4*)sW;
        #pragma unroll
        for (int i = 0; i < 16; i++) sW4[tid + i * 256] = W4[tid + i * 256];
    }

    const int tc = tid & 15;   // cols 8*tc .. 8*tc+7
    const int tr = tid >> 4;   // rows 4*tr .. 4*tr+3

    unsigned long long initc[4];
    if (cvec) {
        #pragma unroll
        for (int p = 0; p < 4; p++) {
            float2 cv2 = *(const float2*)(cvec + 8 * tc + 2 * p);
            asm("mov.b64 %0, {%1, %2};" : "=l"(initc[p]) : "f"(cv2.x), "f"(cv2.y));
        }
    } else {
        #pragma unroll
        for (int p = 0; p < 4; p++) initc[p] = 0ull;
    }

    const int ntiles = (Mrows + 63) >> 6;
    for (int tile = blockIdx.x; tile < ntiles; tile += gridDim.x) {
        const int base = tile << 6;
        __syncthreads();
        #pragma unroll
        for (int i = 0; i < 8; i++) {
            int f4 = tid + i * 256;
            int r = f4 >> 5;
            int c4 = f4 & 31;
            int grow = base + r;
            float4 v = make_float4(0.f, 0.f, 0.f, 0.f);
            if (grow < Mrows) {
                int irow = remap ? ((grow & 1) * N_NODES + (grow >> 1)) : grow;
                v = ((const float4*)A)[(size_t)irow * 32 + c4];
            }
            ((float4*)sA)[f4] = v;
        }
        __syncthreads();

        unsigned long long acc[4][4];
        #pragma unroll
        for (int r = 0; r < 4; r++)
            #pragma unroll
            for (int p = 0; p < 4; p++) acc[r][p] = initc[p];

        const float* aBase = sA + (tr << 2) * FDIM;
        #pragma unroll 2
        for (int k0 = 0; k0 < FDIM; k0 += 4) {
            float4 a0 = *(const float4*)(aBase + k0);
            float4 a1 = *(const float4*)(aBase + FDIM + k0);
            float4 a2 = *(const float4*)(aBase + 2 * FDIM + k0);
            float4 a3 = *(const float4*)(aBase + 3 * FDIM + k0);
            float am[4][4] = {{a0.x, a0.y, a0.z, a0.w}, {a1.x, a1.y, a1.z, a1.w},
                              {a2.x, a2.y, a2.z, a2.w}, {a3.x, a3.y, a3.z, a3.w}};
            #pragma unroll
            for (int kk = 0; kk < 4; kk++) {
                const ulonglong2* bp = (const ulonglong2*)(sW + (k0 + kk) * FDIM + (tc << 3));
                ulonglong2 b01 = bp[0];
                ulonglong2 b23 = bp[1];
                unsigned long long bv[4] = {b01.x, b01.y, b23.x, b23.y};
                unsigned long long pa[4];
                #pragma unroll
                for (int r = 0; r < 4; r++)
                    asm("mov.b64 %0, {%1, %1};" : "=l"(pa[r]) : "f"(am[r][kk]));
                #pragma unroll
                for (int r = 0; r < 4; r++)
                    #pragma unroll
                    for (int p = 0; p < 4; p++)
                        asm("fma.rn.f32x2 %0, %1, %2, %0;"
                            : "+l"(acc[r][p]) : "l"(pa[r]), "l"(bv[p]));
            }
        }

        #pragma unroll
        for (int r = 0; r < 4; r++) {
            int grow = base + (tr << 2) + r;
            if (grow < Mrows) {
                uint4 st;
                unsigned hh[4];
                #pragma unroll
                for (int p = 0; p < 4; p++) {
                    float lo, hi;
                    asm("mov.b64 {%0, %1}, %2;" : "=f"(lo), "=f"(hi) : "l"(acc[r][p]));
                    __half2 h = __floats2half2_rn(lo, hi);
                    hh[p] = *(unsigned*)&h;
                }
                st.x = hh[0]; st.y = hh[1]; st.z = hh[2]; st.w = hh[3];
                *(uint4*)(C + (size_t)grow * FDIM + (tc << 3)) = st;
            }
        }
    }
}

// ---------------- fused aggregate (BOTH batches) + self + bias + relu + BN ---
// Lane-owns-features scheme: one edge payload (2 rows x 128 fp16 = 512B) is
// exactly 32 lanes x 16B -> ONE LDG.128 per lane per edge. Lane l handles
// batch (l>>4), features 8*(l&15)..+8. Halves payload request count.
__device__ __forceinline__ void h8f(uint4 u, float4& A, float4& B) {
    float2 f0 = __half22float2(*(__half2*)&u.x);
    float2 f1 = __half22float2(*(__half2*)&u.y);
    float2 f2 = __half22float2(*(__half2*)&u.z);
    float2 f3 = __half22float2(*(__half2*)&u.w);
    A = make_float4(f0.x, f0.y, f1.x, f1.y);
    B = make_float4(f2.x, f2.y, f3.x, f3.y);
}

__global__ __launch_bounds__(256) void k_agg(const __half* __restrict__ xwi,
                                             const uint2* __restrict__ edge,
                                             const int* __restrict__ start,
                                             const float* __restrict__ dinv,
                                             const float* __restrict__ bias,
                                             float* __restrict__ ti,
                                             float* __restrict__ gsum,
                                             float* __restrict__ gsq) {
    const int tid = threadIdx.x;
    const int lane = tid & 31;
    const int fg = lane & 15;          // feature group: features 8*fg .. 8*fg+7
    const int gw = (blockIdx.x * blockDim.x + tid) >> 5;
    const int nwarps = (gridDim.x * blockDim.x) >> 5;
    const float4 bv0 = ((const float4*)bias)[fg * 2];
    const float4 bv1 = ((const float4*)bias)[fg * 2 + 1];
    float s[8] = {0.f, 0.f, 0.f, 0.f, 0.f, 0.f, 0.f, 0.f};
    float q[8] = {0.f, 0.f, 0.f, 0.f, 0.f, 0.f, 0.f, 0.f};

    for (int n = gw; n < N_NODES; n += nwarps) {
        const int st = start[n];
        const int en = start[n + 1];
        const float d = dinv[n];
        const float d2 = d * d;
        const uint4* blk = (const uint4*)(xwi + (size_t)(2 * n) * FDIM);  // 32 x 16B
        float4 sv0, sv1;
        h8f(__ldg(blk + lane), sv0, sv1);
        float4 acc0 = make_float4(d2 * sv0.x, d2 * sv0.y, d2 * sv0.z, d2 * sv0.w);
        float4 acc1 = make_float4(d2 * sv1.x, d2 * sv1.y, d2 * sv1.z, d2 * sv1.w);

        const int cnt4 = (en - st) >> 2;
        int e = st;
        if (cnt4 > 0) {
            uint2 m0 = __ldg(&edge[e]);
            uint2 m1 = __ldg(&edge[e + 1]);
            uint2 m2 = __ldg(&edge[e + 2]);
            uint2 m3 = __ldg(&edge[e + 3]);
            for (int g = 0; g < cnt4; g++) {
                uint2 p0, p1, p2, p3;
                const int ne = e + 4;
                if (g + 1 < cnt4) {             // prefetch next group's metadata
                    p0 = __ldg(&edge[ne]);
                    p1 = __ldg(&edge[ne + 1]);
                    p2 = __ldg(&edge[ne + 2]);
                    p3 = __ldg(&edge[ne + 3]);
                }
                uint4 e0 = __ldg((const uint4*)(xwi + (size_t)(2 * m0.x) * FDIM) + lane);
                uint4 e1 = __ldg((const uint4*)(xwi + (size_t)(2 * m1.x) * FDIM) + lane);
                uint4 e2 = __ldg((const uint4*)(xwi + (size_t)(2 * m2.x) * FDIM) + lane);
                uint4 e3 = __ldg((const uint4*)(xwi + (size_t)(2 * m3.x) * FDIM) + lane);
                float w0 = __uint_as_float(m0.y), w1 = __uint_as_float(m1.y);
                float w2 = __uint_as_float(m2.y), w3 = __uint_as_float(m3.y);
                float4 aA, aB;
                h8f(e0, aA, aB);
                acc0.x = fmaf(w0, aA.x, acc0.x); acc0.y = fmaf(w0, aA.y, acc0.y);
                acc0.z = fmaf(w0, aA.z, acc0.z); acc0.w = fmaf(w0, aA.w, acc0.w);
                acc1.x = fmaf(w0, aB.x, acc1.x); acc1.y = fmaf(w0, aB.y, acc1.y);
                acc1.z = fmaf(w0, aB.z, acc1.z); acc1.w = fmaf(w0, aB.w, acc1.w);
                h8f(e1, aA, aB);
                acc0.x = fmaf(w1, aA.x, acc0.x); acc0.y = fmaf(w1, aA.y, acc0.y);
                acc0.z = fmaf(w1, aA.z, acc0.z); acc0.w = fmaf(w1, aA.w, acc0.w);
                acc1.x = fmaf(w1, aB.x, acc1.x); acc1.y = fmaf(w1, aB.y, acc1.y);
                acc1.z = fmaf(w1, aB.z, acc1.z); acc1.w = fmaf(w1, aB.w, acc1.w);
                h8f(e2, aA, aB);
                acc0.x = fmaf(w2, aA.x, acc0.x); acc0.y = fmaf(w2, aA.y, acc0.y);
                acc0.z = fmaf(w2, aA.z, acc0.z); acc0.w = fmaf(w2, aA.w, acc0.w);
                acc1.x = fmaf(w2, aB.x, acc1.x); acc1.y = fmaf(w2, aB.y, acc1.y);
                acc1.z = fmaf(w2, aB.z, acc1.z); acc1.w = fmaf(w2, aB.w, acc1.w);
                h8f(e3, aA, aB);
                acc0.x = fmaf(w3, aA.x, acc0.x); acc0.y = fmaf(w3, aA.y, acc0.y);
                acc0.z = fmaf(w3, aA.z, acc0.z); acc0.w = fmaf(w3, aA.w, acc0.w);
                acc1.x = fmaf(w3, aB.x, acc1.x); acc1.y = fmaf(w3, aB.y, acc1.y);
                acc1.z = fmaf(w3, aB.z, acc1.z); acc1.w = fmaf(w3, aB.w, acc1.w);
                m0 = p0; m1 = p1; m2 = p2; m3 = p3;
                e = ne;
            }
        }
        for (; e < en; e++) {
            uint2 m = __ldg(&edge[e]);
            uint4 ev = __ldg((const uint4*)(xwi + (size_t)(2 * m.x) * FDIM) + lane);
            float w = __uint_as_float(m.y);
            float4 aA, aB;
            h8f(ev, aA, aB);
            acc0.x = fmaf(w, aA.x, acc0.x); acc0.y = fmaf(w, aA.y, acc0.y);
            acc0.z = fmaf(w, aA.z, acc0.z); acc0.w = fmaf(w, aA.w, acc0.w);
            acc1.x = fmaf(w, aB.x, acc1.x); acc1.y = fmaf(w, aB.y, acc1.y);
            acc1.z = fmaf(w, aB.z, acc1.z); acc1.w = fmaf(w, aB.w, acc1.w);
        }

        float4 o0, o1;
        o0.x = fmaxf(acc0.x + bv0.x, 0.f);
        o0.y = fmaxf(acc0.y + bv0.y, 0.f);
        o0.z = fmaxf(acc0.z + bv0.z, 0.f);
        o0.w = fmaxf(acc0.w + bv0.w, 0.f);
        o1.x = fmaxf(acc1.x + bv1.x, 0.f);
        o1.y = fmaxf(acc1.y + bv1.y, 0.f);
        o1.z = fmaxf(acc1.z + bv1.z, 0.f);
        o1.w = fmaxf(acc1.w + bv1.w, 0.f);
        // lane l writes features 8*fg..+8 of row (2n + (l>>4)) -> 2 consecutive float4
        float4* dst = (float4*)(ti + (size_t)(2 * n) * FDIM);
        dst[lane * 2] = o0;
        dst[lane * 2 + 1] = o1;
        s[0] += o0.x; q[0] += o0.x * o0.x;
        s[1] += o0.y; q[1] += o0.y * o0.y;
        s[2] += o0.z; q[2] += o0.z * o0.z;
        s[3] += o0.w; q[3] += o0.w * o0.w;
        s[4] += o1.x; q[4] += o1.x * o1.x;
        s[5] += o1.y; q[5] += o1.y * o1.y;
        s[6] += o1.z; q[6] += o1.z * o1.z;
        s[7] += o1.w; q[7] += o1.w * o1.w;
    }

    // BN-stat reduction: thread group fg = tid&15 owns features 8*fg..+8
    __shared__ float sh[256 * 16];
    #pragma unroll
    for (int j = 0; j < 8; j++) { sh[tid * 16 + j] = s[j]; sh[tid * 16 + 8 + j] = q[j]; }
    __syncthreads();
    if (tid < FDIM) {   // thread tid reduces feature tid
        const int fgr = tid >> 3;
        const int j = tid & 7;
        float as = 0.f, aq = 0.f;
        #pragma unroll
        for (int k = 0; k < 16; k++) {
            int src = (k * 16 + fgr) * 16;
            as += sh[src + j];
            aq += sh[src + 8 + j];
        }
        atomicAdd(&gsum[tid], as);
        atomicAdd(&gsq[tid], aq);
    }
}

// ---------------- fold BN into next weight matrix ----------------------------
__global__ void k_fold(const float* __restrict__ gsum, const float* __restrict__ gsq,
                       const float* __restrict__ gamma, const float* __restrict__ beta,
                       const float* __restrict__ Wsrc, int J,
                       const float* __restrict__ extra_bias,
                       float* __restrict__ Wp, float* __restrict__ cv) {
    __shared__ float ssc[FDIM], ssh[FDIM];
    int t = threadIdx.x;  // 128
    float mu = gsum[t] * (1.0f / M_ROWS);
    float var = gsq[t] * (1.0f / M_ROWS) - mu * mu;
    float sc = gamma[t] * rsqrtf(var + EPSBN);
    ssc[t] = sc;
    ssh[t] = beta[t] - mu * sc;
    __syncthreads();
    if (t < J) {
        float acc = extra_bias ? extra_bias[t] : 0.f;
        for (int k = 0; k < FDIM; k++) {
            float w = Wsrc[k * J + t];
            Wp[k * J + t] = ssc[k] * w;
            acc += ssh[k] * w;
        }
        cv[t] = acc;
    }
}

// ---------------- classifier: out = t2 @ Wcp + bcp (un-interleaves) ----------
__global__ void k_classifier(const float* __restrict__ t2, const float* __restrict__ Wcp,
                             const float* __restrict__ bcp, float* __restrict__ out) {
    __shared__ float sWT[OUT_DIM * FDIM];  // [o][k]
    __shared__ float sb[OUT_DIM];
    int tid = threadIdx.x;  // 256
    for (int i = tid; i < FDIM * OUT_DIM; i += 256) {
        int k = i / OUT_DIM, o = i % OUT_DIM;
        sWT[o * FDIM + k] = Wcp[i];
    }
    if (tid < OUT_DIM) sb[tid] = bcp[tid];
    __syncthreads();

    int gt = blockIdx.x * blockDim.x + tid;
    int warp = gt >> 5;
    int lane = gt & 31;
    int nw = (gridDim.x * blockDim.x) >> 5;
    for (int rowJ = warp; rowJ < M_ROWS; rowJ += nw) {
        float4 v = __ldg((const float4*)(t2 + (size_t)rowJ * FDIM) + lane);
        float y[OUT_DIM];
        #pragma unroll
        for (int o = 0; o < OUT_DIM; o++) {
            float4 w = ((const float4*)(sWT + o * FDIM))[lane];
            y[o] = v.x * w.x + v.y * w.y + v.z * w.z + v.w * w.w;
        }
        #pragma unroll
        for (int off = 16; off; off >>= 1)
            #pragma unroll
            for (int o = 0; o < OUT_DIM; o++)
                y[o] += __shfl_xor_sync(0xffffffffu, y[o], off);
        if (lane < OUT_DIM) {
            int n = rowJ >> 1, b = rowJ & 1;
            out[(size_t)(b * N_NODES + n) * OUT_DIM + lane] = y[lane] + sb[lane];
        }
    }
}

// ---------------- launch -----------------------------------------------------
extern "C" void kernel_launch(void* const* d_in, const int* in_sizes, int n_in,
                              void* d_out, int out_size) {
    const float* x   = (const float*)d_in[0];
    const int*   ei  = (const int*)d_in[1];
    const float* ewp = (const float*)d_in[2];
    const float* W1  = (const float*)d_in[3];
    const float* b1  = (const float*)d_in[4];
    const float* W2  = (const float*)d_in[5];
    const float* b2  = (const float*)d_in[6];
    const float* g1  = (const float*)d_in[7];
    const float* be1 = (const float*)d_in[8];
    const float* g2  = (const float*)d_in[9];
    const float* be2 = (const float*)d_in[10];
    const float* Wc  = (const float*)d_in[11];
    const float* bc  = (const float*)d_in[12];
    float* out = (float*)d_out;
    const int* row = ei;
    const int* col = ei + N_EDGES;

    float *p_t, *p_dinv, *p_deg;
    float *p_W2p, *p_cvec, *p_Wcp, *p_bcp, *p_sum, *p_sq;
    int *p_cnt, *p_start, *p_cursor, *p_partial, *p_pscan;
    uint2* p_edge;
    __half* p_xw;
    cudaGetSymbolAddress((void**)&p_xw,   g_xw);
    cudaGetSymbolAddress((void**)&p_t,    g_t);
    cudaGetSymbolAddress((void**)&p_dinv, g_dinv);
    cudaGetSymbolAddress((void**)&p_deg,  g_deg);
    cudaGetSymbolAddress((void**)&p_cnt,  g_cnt);
    cudaGetSymbolAddress((void**)&p_start, g_start);
    cudaGetSymbolAddress((void**)&p_cursor, g_cursor);
    cudaGetSymbolAddress((void**)&p_partial, g_partial);
    cudaGetSymbolAddress((void**)&p_pscan, g_pscan);
    cudaGetSymbolAddress((void**)&p_edge, g_edge);
    cudaGetSymbolAddress((void**)&p_W2p,  g_W2p);
    cudaGetSymbolAddress((void**)&p_cvec, g_cvec);
    cudaGetSymbolAddress((void**)&p_Wcp,  g_Wcp);
    cudaGetSymbolAddress((void**)&p_bcp,  g_bcp);
    cudaGetSymbolAddress((void**)&p_sum,  g_sum);
    cudaGetSymbolAddress((void**)&p_sq,   g_sq);

    (void)cudaFuncSetAttribute(k_gemm128, cudaFuncAttributeMaxDynamicSharedMemorySize, 98304);

    // --- CSR build + layer-1 GEMM ---
    k_init      <<<(N_NODES + 255) / 256, 256>>>(p_deg, p_cnt);
    k_pass1     <<<(N_EDGES + 255) / 256, 256>>>(ewp, col, p_deg, p_cnt);
    k_dinv      <<<(N_NODES + 255) / 256, 256>>>(p_deg, p_dinv);
    k_scan1     <<<NBLK_SCAN, 256>>>(p_cnt, p_partial);
    k_scan2     <<<1, 256>>>(p_partial, p_pscan, p_start);
    k_gemm128   <<<592, 256, 98304>>>(x, W1, nullptr, p_xw, M_ROWS, 1);
    k_scan3     <<<NBLK_SCAN, 256>>>(p_cnt, p_pscan, p_start, p_cursor);
    k_sortedges <<<(N_EDGES + 255) / 256, 256>>>(ewp, row, col, p_dinv, p_cursor, p_edge);

    // --- layer 1 aggregation (both batches in one pass) ---
    cudaMemsetAsync(p_sum, 0, FDIM * sizeof(float), 0);
    cudaMemsetAsync(p_sq,  0, FDIM * sizeof(float), 0);
    k_agg<<<1184, 256>>>(p_xw, p_edge, p_start, p_dinv, b1, p_t, p_sum, p_sq);
    k_fold<<<1, 128>>>(p_sum, p_sq, g1, be1, W2, FDIM, nullptr, p_W2p, p_cvec);

    // --- layer 2 (BN1 folded into W2; t interleaved fp32 -> no remap) ---
    k_gemm128<<<592, 256, 98304>>>(p_t, p_W2p, p_cvec, p_xw, M_ROWS, 0);
    cudaMemsetAsync(p_sum, 0, FDIM * sizeof(float), 0);
    cudaMemsetAsync(p_sq,  0, FDIM * sizeof(float), 0);
    k_agg<<<1184, 256>>>(p_xw, p_edge, p_start, p_dinv, b2, p_t, p_sum, p_sq);
    k_fold<<<1, 128>>>(p_sum, p_sq, g2, be2, Wc, OUT_DIM, bc, p_Wcp, p_bcp);

    // --- classifier (BN2 folded into Wc; un-interleaves on store) ---
    k_classifier<<<1024, 256>>>(p_t, p_Wcp, p_bcp, out);
}

// round 13
// speedup vs baseline: 2.9503x; 1.5135x over previous
#include <cuda_runtime.h>
#include <cuda_fp16.h>
#include <cstdint>

#define N_NODES 50000
#define N_EDGES 640000
#define FDIM    128
#define OUT_DIM 16
#define BATCH   2
#define M_ROWS  (BATCH * N_NODES)   /* 100000 flattened rows */
#define EPSBN   1e-5f
#define NBLK_SCAN ((N_NODES + 255) / 256)   /* 196 */
#define SROW 136                     /* padded fp16 row stride (272B) */

// ---------------- scratch (device globals; no allocation allowed) -------------
__device__ __align__(128) __half g_xw [(size_t)M_ROWS * FDIM];  // GEMM outputs, fp16, interleaved [n][b][128]
__device__ __align__(128) float g_t   [(size_t)M_ROWS * FDIM];  // relu(conv) activations (fp32, interleaved)
__device__ __align__(128) float g_dinv[N_NODES];
__device__ __align__(128) float g_deg [N_NODES];
__device__ __align__(128) int   g_cnt   [N_NODES];
__device__ __align__(128) int   g_start [N_NODES + 1];
__device__ __align__(128) int   g_cursor[N_NODES];
__device__ __align__(128) int   g_partial[256];
__device__ __align__(128) int   g_pscan  [256];
__device__ __align__(128) uint2 g_edge  [N_EDGES];              // {src, norm-bits} sorted by dst
__device__ __align__(128) float g_W2p [FDIM * FDIM];
__device__ __align__(128) float g_cvec[FDIM];
__device__ __align__(128) float g_Wcp [FDIM * OUT_DIM];
__device__ __align__(128) float g_bcp [OUT_DIM];
__device__ __align__(128) float g_sum [FDIM];
__device__ __align__(128) float g_sq  [FDIM];

// ---------------- init: deg=1 (self loop), cnt=0 ----------------------------
__global__ void k_init(float* deg, int* cnt) {
    int i = blockIdx.x * blockDim.x + threadIdx.x;
    if (i < N_NODES) { deg[i] = 1.0f; cnt[i] = 0; }
}

__global__ void k_pass1(const float* __restrict__ ewp, const int* __restrict__ col,
                        float* deg, int* cnt) {
    int e = blockIdx.x * blockDim.x + threadIdx.x;
    if (e < N_EDGES) {
        int c = col[e];
        atomicAdd(&deg[c], expf(ewp[e]));
        atomicAdd(&cnt[c], 1);
    }
}

__global__ void k_dinv(const float* __restrict__ deg, float* dinv) {
    int i = blockIdx.x * blockDim.x + threadIdx.x;
    if (i < N_NODES) {
        float d = deg[i];
        dinv[i] = (d > 0.f) ? rsqrtf(d) : 0.f;
    }
}

// ---------------- hierarchical scan (3 kernels, all coalesced) ---------------
__global__ void k_scan1(const int* __restrict__ cnt, int* __restrict__ partial) {
    __shared__ int sh[8];
    int idx = blockIdx.x * 256 + threadIdx.x;
    int v = (idx < N_NODES) ? cnt[idx] : 0;
    #pragma unroll
    for (int off = 16; off; off >>= 1) v += __shfl_down_sync(0xffffffffu, v, off);
    if ((threadIdx.x & 31) == 0) sh[threadIdx.x >> 5] = v;
    __syncthreads();
    if (threadIdx.x == 0) {
        int s = 0;
        #pragma unroll
        for (int w = 0; w < 8; w++) s += sh[w];
        partial[blockIdx.x] = s;
    }
}

__global__ void k_scan2(const int* __restrict__ partial, int* __restrict__ pscan,
                        int* __restrict__ start) {
    __shared__ int sh[256];
    int t = threadIdx.x;
    int v = (t < NBLK_SCAN) ? partial[t] : 0;
    sh[t] = v;
    __syncthreads();
    #pragma unroll
    for (int off = 1; off < 256; off <<= 1) {
        int u = (t >= off) ? sh[t - off] : 0;
        __syncthreads();
        sh[t] += u;
        __syncthreads();
    }
    if (t < NBLK_SCAN) pscan[t] = sh[t] - v;   // exclusive
    if (t == 0) start[N_NODES] = N_EDGES;
}

__global__ void k_scan3(const int* __restrict__ cnt, const int* __restrict__ pscan,
                        int* __restrict__ start, int* __restrict__ cursor) {
    __shared__ int sh[256];
    int t = threadIdx.x;
    int idx = blockIdx.x * 256 + t;
    int v = (idx < N_NODES) ? cnt[idx] : 0;
    sh[t] = v;
    __syncthreads();
    #pragma unroll
    for (int off = 1; off < 256; off <<= 1) {
        int u = (t >= off) ? sh[t - off] : 0;
        __syncthreads();
        sh[t] += u;
        __syncthreads();
    }
    if (idx < N_NODES) {
        int excl = sh[t] - v + pscan[blockIdx.x];
        start[idx] = excl;
        cursor[idx] = excl;
    }
}

// ---------------- bucket scatter: sorted {src, norm} per destination ---------
__global__ void k_sortedges(const float* __restrict__ ewp, const int* __restrict__ row,
                            const int* __restrict__ col, const float* __restrict__ dinv,
                            int* cursor, uint2* __restrict__ edge) {
    int e = blockIdx.x * blockDim.x + threadIdx.x;
    if (e < N_EDGES) {
        int r = row[e];
        int c = col[e];
        float nm = dinv[r] * expf(ewp[e]) * dinv[c];
        int pos = atomicAdd(&cursor[c], 1);
        edge[pos] = make_uint2((unsigned)r, __float_as_uint(nm));
    }
}

// ---------------- tensor-core GEMM: C_half = A(f32->f16) @ W(f32->f16) + cvec
// mma.sync.m16n8k16, fp32 accumulate, fp16 output. Block tile 128x128, K=128
// fully smem-resident. 8 warps: warp (wm, wn) computes rows 32*wm, cols 64*wn.
__device__ __forceinline__ uint32_t smem_u32(const void* p) {
    return (uint32_t)__cvta_generic_to_shared(p);
}

__global__ __launch_bounds__(256) void k_gemm_mma(const float* __restrict__ A,
                                                  const float* __restrict__ W,
                                                  const float* __restrict__ cvec,
                                                  __half* __restrict__ C, int Mrows,
                                                  int remap) {
    extern __shared__ __half smh[];
    __half* sA = smh;                       // [128][SROW]
    __half* sW = smh + 128 * SROW;          // [128][SROW]
    float* scv = (float*)(sW + 128 * SROW); // [128]
    const int tid = threadIdx.x;
    const int wid = tid >> 5, lane = tid & 31;
    const int wm = wid >> 1;                // 0..3
    const int wn = wid & 1;                 // 0..1

    // load W (fp32 -> fp16) + cvec once per block
    for (int i = tid; i < 2048; i += 256) {             // 128 rows x 16 chunks
        int r = i >> 4, c8 = i & 15;
        float4 w0 = __ldg((const float4*)W + r * 32 + c8 * 2);
        float4 w1 = __ldg((const float4*)W + r * 32 + c8 * 2 + 1);
        __half2 h[4];
        h[0] = __floats2half2_rn(w0.x, w0.y);
        h[1] = __floats2half2_rn(w0.z, w0.w);
        h[2] = __floats2half2_rn(w1.x, w1.y);
        h[3] = __floats2half2_rn(w1.z, w1.w);
        *(uint4*)(sW + r * SROW + c8 * 8) = *(uint4*)h;
    }
    if (tid < FDIM) scv[tid] = cvec ? cvec[tid] : 0.f;

    const int ntile = (Mrows + 127) >> 7;
    for (int tile = blockIdx.x; tile < ntile; tile += gridDim.x) {
        const int base = tile << 7;
        __syncthreads();    // previous iter reads done; W/cvec writes ordered (iter 0)
        for (int i = tid; i < 2048; i += 256) {
            int r = i >> 4, c8 = i & 15;
            int grow = base + r;
            uint4 st = make_uint4(0u, 0u, 0u, 0u);
            if (grow < Mrows) {
                int irow = remap ? ((grow & 1) * N_NODES + (grow >> 1)) : grow;
                float4 a0 = __ldg((const float4*)A + (size_t)irow * 32 + c8 * 2);
                float4 a1 = __ldg((const float4*)A + (size_t)irow * 32 + c8 * 2 + 1);
                __half2 h[4];
                h[0] = __floats2half2_rn(a0.x, a0.y);
                h[1] = __floats2half2_rn(a0.z, a0.w);
                h[2] = __floats2half2_rn(a1.x, a1.y);
                h[3] = __floats2half2_rn(a1.z, a1.w);
                st = *(uint4*)h;
            }
            *(uint4*)(sA + r * SROW + c8 * 8) = st;
        }
        __syncthreads();

        float acc[2][8][4];
        #pragma unroll
        for (int mt = 0; mt < 2; mt++)
            #pragma unroll
            for (int nt = 0; nt < 8; nt++)
                #pragma unroll
                for (int k = 0; k < 4; k++) acc[mt][nt][k] = 0.f;

        #pragma unroll
        for (int ks = 0; ks < 8; ks++) {
            const int k0 = ks * 16;
            // A fragments: 2 m16 tiles
            uint32_t a[2][4];
            #pragma unroll
            for (int mt = 0; mt < 2; mt++) {
                int r = wm * 32 + mt * 16 + (lane & 15);
                int kk = k0 + ((lane & 16) ? 8 : 0);
                uint32_t addr = smem_u32(sA + r * SROW + kk);
                asm volatile("ldmatrix.sync.aligned.m8n8.x4.shared.b16 {%0,%1,%2,%3}, [%4];"
                             : "=r"(a[mt][0]), "=r"(a[mt][1]), "=r"(a[mt][2]), "=r"(a[mt][3])
                             : "r"(addr));
            }
            // B fragments: 8 n8 tiles via 4 x (ldmatrix.x4.trans covering n16)
            uint32_t b[8][2];
            #pragma unroll
            for (int np = 0; np < 4; np++) {
                int r = k0 + (lane & 15);
                int cc = wn * 64 + np * 16 + ((lane & 16) ? 8 : 0);
                uint32_t addr = smem_u32(sW + r * SROW + cc);
                uint32_t r0, r1, r2, r3;
                asm volatile("ldmatrix.sync.aligned.m8n8.x4.trans.shared.b16 {%0,%1,%2,%3}, [%4];"
                             : "=r"(r0), "=r"(r1), "=r"(r2), "=r"(r3)
                             : "r"(addr));
                b[np * 2][0] = r0;     b[np * 2][1] = r1;
                b[np * 2 + 1][0] = r2; b[np * 2 + 1][1] = r3;
            }
            #pragma unroll
            for (int mt = 0; mt < 2; mt++)
                #pragma unroll
                for (int nt = 0; nt < 8; nt++)
                    asm volatile("mma.sync.aligned.m16n8k16.row.col.f32.f16.f16.f32 "
                                 "{%0,%1,%2,%3}, {%4,%5,%6,%7}, {%8,%9}, {%0,%1,%2,%3};"
                                 : "+f"(acc[mt][nt][0]), "+f"(acc[mt][nt][1]),
                                   "+f"(acc[mt][nt][2]), "+f"(acc[mt][nt][3])
                                 : "r"(a[mt][0]), "r"(a[mt][1]), "r"(a[mt][2]), "r"(a[mt][3]),
                                   "r"(b[nt][0]), "r"(b[nt][1]));
        }

        // epilogue: + cvec, pack fp16, store
        #pragma unroll
        for (int mt = 0; mt < 2; mt++) {
            int r0 = base + wm * 32 + mt * 16 + (lane >> 2);
            int r1 = r0 + 8;
            #pragma unroll
            for (int nt = 0; nt < 8; nt++) {
                int cc = wn * 64 + nt * 8 + (lane & 3) * 2;
                float cv0 = scv[cc], cv1 = scv[cc + 1];
                if (r0 < Mrows) {
                    __half2 h = __floats2half2_rn(acc[mt][nt][0] + cv0, acc[mt][nt][1] + cv1);
                    *(__half2*)(C + (size_t)r0 * FDIM + cc) = h;
                }
                if (r1 < Mrows) {
                    __half2 h = __floats2half2_rn(acc[mt][nt][2] + cv0, acc[mt][nt][3] + cv1);
                    *(__half2*)(C + (size_t)r1 * FDIM + cc) = h;
                }
            }
        }
    }
}

// ---------------- fused aggregate (BOTH batches) + self + bias + relu + BN ---
__device__ __forceinline__ void h8f(uint4 u, float4& A, float4& B) {
    float2 f0 = __half22float2(*(__half2*)&u.x);
    float2 f1 = __half22float2(*(__half2*)&u.y);
    float2 f2 = __half22float2(*(__half2*)&u.z);
    float2 f3 = __half22float2(*(__half2*)&u.w);
    A = make_float4(f0.x, f0.y, f1.x, f1.y);
    B = make_float4(f2.x, f2.y, f3.x, f3.y);
}

__global__ __launch_bounds__(256) void k_agg(const __half* __restrict__ xwi,
                                             const uint2* __restrict__ edge,
                                             const int* __restrict__ start,
                                             const float* __restrict__ dinv,
                                             const float* __restrict__ bias,
                                             float* __restrict__ ti,
                                             float* __restrict__ gsum,
                                             float* __restrict__ gsq) {
    const int tid = threadIdx.x;
    const int lane = tid & 31;
    const int fg = lane & 15;          // feature group: features 8*fg .. 8*fg+7
    const int gw = (blockIdx.x * blockDim.x + tid) >> 5;
    const int nwarps = (gridDim.x * blockDim.x) >> 5;
    const float4 bv0 = ((const float4*)bias)[fg * 2];
    const float4 bv1 = ((const float4*)bias)[fg * 2 + 1];
    float s[8] = {0.f, 0.f, 0.f, 0.f, 0.f, 0.f, 0.f, 0.f};
    float q[8] = {0.f, 0.f, 0.f, 0.f, 0.f, 0.f, 0.f, 0.f};

    for (int n = gw; n < N_NODES; n += nwarps) {
        const int st = start[n];
        const int en = start[n + 1];
        const float d = dinv[n];
        const float d2 = d * d;
        const uint4* blk = (const uint4*)(xwi + (size_t)(2 * n) * FDIM);
        float4 sv0, sv1;
        h8f(__ldg(blk + lane), sv0, sv1);
        float4 acc0 = make_float4(d2 * sv0.x, d2 * sv0.y, d2 * sv0.z, d2 * sv0.w);
        float4 acc1 = make_float4(d2 * sv1.x, d2 * sv1.y, d2 * sv1.z, d2 * sv1.w);

        const int cnt4 = (en - st) >> 2;
        int e = st;
        if (cnt4 > 0) {
            uint2 m0 = __ldg(&edge[e]);
            uint2 m1 = __ldg(&edge[e + 1]);
            uint2 m2 = __ldg(&edge[e + 2]);
            uint2 m3 = __ldg(&edge[e + 3]);
            for (int g = 0; g < cnt4; g++) {
                uint2 p0, p1, p2, p3;
                const int ne = e + 4;
                if (g + 1 < cnt4) {
                    p0 = __ldg(&edge[ne]);
                    p1 = __ldg(&edge[ne + 1]);
                    p2 = __ldg(&edge[ne + 2]);
                    p3 = __ldg(&edge[ne + 3]);
                }
                uint4 e0 = __ldg((const uint4*)(xwi + (size_t)(2 * m0.x) * FDIM) + lane);
                uint4 e1 = __ldg((const uint4*)(xwi + (size_t)(2 * m1.x) * FDIM) + lane);
                uint4 e2 = __ldg((const uint4*)(xwi + (size_t)(2 * m2.x) * FDIM) + lane);
                uint4 e3 = __ldg((const uint4*)(xwi + (size_t)(2 * m3.x) * FDIM) + lane);
                float w0 = __uint_as_float(m0.y), w1 = __uint_as_float(m1.y);
                float w2 = __uint_as_float(m2.y), w3 = __uint_as_float(m3.y);
                float4 aA, aB;
                h8f(e0, aA, aB);
                acc0.x = fmaf(w0, aA.x, acc0.x); acc0.y = fmaf(w0, aA.y, acc0.y);
                acc0.z = fmaf(w0, aA.z, acc0.z); acc0.w = fmaf(w0, aA.w, acc0.w);
                acc1.x = fmaf(w0, aB.x, acc1.x); acc1.y = fmaf(w0, aB.y, acc1.y);
                acc1.z = fmaf(w0, aB.z, acc1.z); acc1.w = fmaf(w0, aB.w, acc1.w);
                h8f(e1, aA, aB);
                acc0.x = fmaf(w1, aA.x, acc0.x); acc0.y = fmaf(w1, aA.y, acc0.y);
                acc0.z = fmaf(w1, aA.z, acc0.z); acc0.w = fmaf(w1, aA.w, acc0.w);
                acc1.x = fmaf(w1, aB.x, acc1.x); acc1.y = fmaf(w1, aB.y, acc1.y);
                acc1.z = fmaf(w1, aB.z, acc1.z); acc1.w = fmaf(w1, aB.w, acc1.w);
                h8f(e2, aA, aB);
                acc0.x = fmaf(w2, aA.x, acc0.x); acc0.y = fmaf(w2, aA.y, acc0.y);
                acc0.z = fmaf(w2, aA.z, acc0.z); acc0.w = fmaf(w2, aA.w, acc0.w);
                acc1.x = fmaf(w2, aB.x, acc1.x); acc1.y = fmaf(w2, aB.y, acc1.y);
                acc1.z = fmaf(w2, aB.z, acc1.z); acc1.w = fmaf(w2, aB.w, acc1.w);
                h8f(e3, aA, aB);
                acc0.x = fmaf(w3, aA.x, acc0.x); acc0.y = fmaf(w3, aA.y, acc0.y);
                acc0.z = fmaf(w3, aA.z, acc0.z); acc0.w = fmaf(w3, aA.w, acc0.w);
                acc1.x = fmaf(w3, aB.x, acc1.x); acc1.y = fmaf(w3, aB.y, acc1.y);
                acc1.z = fmaf(w3, aB.z, acc1.z); acc1.w = fmaf(w3, aB.w, acc1.w);
                m0 = p0; m1 = p1; m2 = p2; m3 = p3;
                e = ne;
            }
        }
        for (; e < en; e++) {
            uint2 m = __ldg(&edge[e]);
            uint4 ev = __ldg((const uint4*)(xwi + (size_t)(2 * m.x) * FDIM) + lane);
            float w = __uint_as_float(m.y);
            float4 aA, aB;
            h8f(ev, aA, aB);
            acc0.x = fmaf(w, aA.x, acc0.x); acc0.y = fmaf(w, aA.y, acc0.y);
            acc0.z = fmaf(w, aA.z, acc0.z); acc0.w = fmaf(w, aA.w, acc0.w);
            acc1.x = fmaf(w, aB.x, acc1.x); acc1.y = fmaf(w, aB.y, acc1.y);
            acc1.z = fmaf(w, aB.z, acc1.z); acc1.w = fmaf(w, aB.w, acc1.w);
        }

        float4 o0, o1;
        o0.x = fmaxf(acc0.x + bv0.x, 0.f);
        o0.y = fmaxf(acc0.y + bv0.y, 0.f);
        o0.z = fmaxf(acc0.z + bv0.z, 0.f);
        o0.w = fmaxf(acc0.w + bv0.w, 0.f);
        o1.x = fmaxf(acc1.x + bv1.x, 0.f);
        o1.y = fmaxf(acc1.y + bv1.y, 0.f);
        o1.z = fmaxf(acc1.z + bv1.z, 0.f);
        o1.w = fmaxf(acc1.w + bv1.w, 0.f);
        float4* dst = (float4*)(ti + (size_t)(2 * n) * FDIM);
        dst[lane * 2] = o0;
        dst[lane * 2 + 1] = o1;
        s[0] += o0.x; q[0] += o0.x * o0.x;
        s[1] += o0.y; q[1] += o0.y * o0.y;
        s[2] += o0.z; q[2] += o0.z * o0.z;
        s[3] += o0.w; q[3] += o0.w * o0.w;
        s[4] += o1.x; q[4] += o1.x * o1.x;
        s[5] += o1.y; q[5] += o1.y * o1.y;
        s[6] += o1.z; q[6] += o1.z * o1.z;
        s[7] += o1.w; q[7] += o1.w * o1.w;
    }

    __shared__ float sh[256 * 16];
    #pragma unroll
    for (int j = 0; j < 8; j++) { sh[tid * 16 + j] = s[j]; sh[tid * 16 + 8 + j] = q[j]; }
    __syncthreads();
    if (tid < FDIM) {
        const int fgr = tid >> 3;
        const int j = tid & 7;
        float as = 0.f, aq = 0.f;
        #pragma unroll
        for (int k = 0; k < 16; k++) {
            int src = (k * 16 + fgr) * 16;
            as += sh[src + j];
            aq += sh[src + 8 + j];
        }
        atomicAdd(&gsum[tid], as);
        atomicAdd(&gsq[tid], aq);
    }
}

// ---------------- fold BN into next weight matrix ----------------------------
__global__ void k_fold(const float* __restrict__ gsum, const float* __restrict__ gsq,
                       const float* __restrict__ gamma, const float* __restrict__ beta,
                       const float* __restrict__ Wsrc, int J,
                       const float* __restrict__ extra_bias,
                       float* __restrict__ Wp, float* __restrict__ cv) {
    __shared__ float ssc[FDIM], ssh[FDIM];
    int t = threadIdx.x;  // 128
    float mu = gsum[t] * (1.0f / M_ROWS);
    float var = gsq[t] * (1.0f / M_ROWS) - mu * mu;
    float sc = gamma[t] * rsqrtf(var + EPSBN);
    ssc[t] = sc;
    ssh[t] = beta[t] - mu * sc;
    __syncthreads();
    if (t < J) {
        float acc = extra_bias ? extra_bias[t] : 0.f;
        for (int k = 0; k < FDIM; k++) {
            float w = Wsrc[k * J + t];
            Wp[k * J + t] = ssc[k] * w;
            acc += ssh[k] * w;
        }
        cv[t] = acc;
    }
}

// ---------------- classifier: out = t2 @ Wcp + bcp (un-interleaves) ----------
__global__ void k_classifier(const float* __restrict__ t2, const float* __restrict__ Wcp,
                             const float* __restrict__ bcp, float* __restrict__ out) {
    __shared__ float sWT[OUT_DIM * FDIM];  // [o][k]
    __shared__ float sb[OUT_DIM];
    int tid = threadIdx.x;  // 256
    for (int i = tid; i < FDIM * OUT_DIM; i += 256) {
        int k = i / OUT_DIM, o = i % OUT_DIM;
        sWT[o * FDIM + k] = Wcp[i];
    }
    if (tid < OUT_DIM) sb[tid] = bcp[tid];
    __syncthreads();

    int gt = blockIdx.x * blockDim.x + tid;
    int warp = gt >> 5;
    int lane = gt & 31;
    int nw = (gridDim.x * blockDim.x) >> 5;
    for (int rowJ = warp; rowJ < M_ROWS; rowJ += nw) {
        float4 v = __ldg((const float4*)(t2 + (size_t)rowJ * FDIM) + lane);
        float y[OUT_DIM];
        #pragma unroll
        for (int o = 0; o < OUT_DIM; o++) {
            float4 w = ((const float4*)(sWT + o * FDIM))[lane];
            y[o] = v.x * w.x + v.y * w.y + v.z * w.z + v.w * w.w;
        }
        #pragma unroll
        for (int off = 16; off; off >>= 1)
            #pragma unroll
            for (int o = 0; o < OUT_DIM; o++)
                y[o] += __shfl_xor_sync(0xffffffffu, y[o], off);
        if (lane < OUT_DIM) {
            int n = rowJ >> 1, b = rowJ & 1;
            out[(size_t)(b * N_NODES + n) * OUT_DIM + lane] = y[lane] + sb[lane];
        }
    }
}

// ---------------- launch -----------------------------------------------------
extern "C" void kernel_launch(void* const* d_in, const int* in_sizes, int n_in,
                              void* d_out, int out_size) {
    const float* x   = (const float*)d_in[0];
    const int*   ei  = (const int*)d_in[1];
    const float* ewp = (const float*)d_in[2];
    const float* W1  = (const float*)d_in[3];
    const float* b1  = (const float*)d_in[4];
    const float* W2  = (const float*)d_in[5];
    const float* b2  = (const float*)d_in[6];
    const float* g1  = (const float*)d_in[7];
    const float* be1 = (const float*)d_in[8];
    const float* g2  = (const float*)d_in[9];
    const float* be2 = (const float*)d_in[10];
    const float* Wc  = (const float*)d_in[11];
    const float* bc  = (const float*)d_in[12];
    float* out = (float*)d_out;
    const int* row = ei;
    const int* col = ei + N_EDGES;

    float *p_t, *p_dinv, *p_deg;
    float *p_W2p, *p_cvec, *p_Wcp, *p_bcp, *p_sum, *p_sq;
    int *p_cnt, *p_start, *p_cursor, *p_partial, *p_pscan;
    uint2* p_edge;
    __half* p_xw;
    cudaGetSymbolAddress((void**)&p_xw,   g_xw);
    cudaGetSymbolAddress((void**)&p_t,    g_t);
    cudaGetSymbolAddress((void**)&p_dinv, g_dinv);
    cudaGetSymbolAddress((void**)&p_deg,  g_deg);
    cudaGetSymbolAddress((void**)&p_cnt,  g_cnt);
    cudaGetSymbolAddress((void**)&p_start, g_start);
    cudaGetSymbolAddress((void**)&p_cursor, g_cursor);
    cudaGetSymbolAddress((void**)&p_partial, g_partial);
    cudaGetSymbolAddress((void**)&p_pscan, g_pscan);
    cudaGetSymbolAddress((void**)&p_edge, g_edge);
    cudaGetSymbolAddress((void**)&p_W2p,  g_W2p);
    cudaGetSymbolAddress((void**)&p_cvec, g_cvec);
    cudaGetSymbolAddress((void**)&p_Wcp,  g_Wcp);
    cudaGetSymbolAddress((void**)&p_bcp,  g_bcp);
    cudaGetSymbolAddress((void**)&p_sum,  g_sum);
    cudaGetSymbolAddress((void**)&p_sq,   g_sq);

    const int SMEM_MMA = 2 * 128 * SROW * 2 + FDIM * 4;   // ~70.2 KB
    (void)cudaFuncSetAttribute(k_gemm_mma, cudaFuncAttributeMaxDynamicSharedMemorySize, SMEM_MMA);

    // --- CSR build + layer-1 GEMM ---
    k_init      <<<(N_NODES + 255) / 256, 256>>>(p_deg, p_cnt);
    k_pass1     <<<(N_EDGES + 255) / 256, 256>>>(ewp, col, p_deg, p_cnt);
    k_dinv      <<<(N_NODES + 255) / 256, 256>>>(p_deg, p_dinv);
    k_scan1     <<<NBLK_SCAN, 256>>>(p_cnt, p_partial);
    k_scan2     <<<1, 256>>>(p_partial, p_pscan, p_start);
    k_gemm_mma  <<<782, 256, SMEM_MMA>>>(x, W1, nullptr, p_xw, M_ROWS, 1);
    k_scan3     <<<NBLK_SCAN, 256>>>(p_cnt, p_pscan, p_start, p_cursor);
    k_sortedges <<<(N_EDGES + 255) / 256, 256>>>(ewp, row, col, p_dinv, p_cursor, p_edge);

    // --- layer 1 aggregation (both batches in one pass) ---
    cudaMemsetAsync(p_sum, 0, FDIM * sizeof(float), 0);
    cudaMemsetAsync(p_sq,  0, FDIM * sizeof(float), 0);
    k_agg<<<1184, 256>>>(p_xw, p_edge, p_start, p_dinv, b1, p_t, p_sum, p_sq);
    k_fold<<<1, 128>>>(p_sum, p_sq, g1, be1, W2, FDIM, nullptr, p_W2p, p_cvec);

    // --- layer 2 (BN1 folded into W2; t interleaved fp32 -> no remap) ---
    k_gemm_mma<<<782, 256, SMEM_MMA>>>(p_t, p_W2p, p_cvec, p_xw, M_ROWS, 0);
    cudaMemsetAsync(p_sum, 0, FDIM * sizeof(float), 0);
    cudaMemsetAsync(p_sq,  0, FDIM * sizeof(float), 0);
    k_agg<<<1184, 256>>>(p_xw, p_edge, p_start, p_dinv, b2, p_t, p_sum, p_sq);
    k_fold<<<1, 128>>>(p_sum, p_sq, g2, be2, Wc, OUT_DIM, bc, p_Wcp, p_bcp);

    // --- classifier (BN2 folded into Wc; un-interleaves on store) ---
    k_classifier<<<1024, 256>>>(p_t, p_Wcp, p_bcp, out);
}

// round 14
// speedup vs baseline: 3.0279x; 1.0263x over previous
#include <cuda_runtime.h>
#include <cuda_fp16.h>
#include <cstdint>

#define N_NODES 50000
#define N_EDGES 640000
#define FDIM    128
#define OUT_DIM 16
#define BATCH   2
#define M_ROWS  (BATCH * N_NODES)   /* 100000 flattened rows */
#define EPSBN   1e-5f
#define NBLK_SCAN ((N_NODES + 255) / 256)   /* 196 */
#define SROW 136                     /* padded fp16 row stride (272B) */

// ---------------- scratch (device globals; no allocation allowed) -------------
__device__ __align__(128) __half g_xw [(size_t)M_ROWS * FDIM];  // GEMM outputs, fp16, interleaved [n][b][128]
__device__ __align__(128) __half g_t16[(size_t)M_ROWS * FDIM];  // layer-1 activations, fp16 interleaved
__device__ __align__(128) float g_t   [(size_t)M_ROWS * FDIM];  // layer-2 activations (fp32, interleaved)
__device__ __align__(128) float g_dinv[N_NODES];
__device__ __align__(128) float g_deg [N_NODES];
__device__ __align__(128) int   g_cnt   [N_NODES];
__device__ __align__(128) int   g_start [N_NODES + 1];
__device__ __align__(128) int   g_cursor[N_NODES];
__device__ __align__(128) int   g_partial[256];
__device__ __align__(128) int   g_pscan  [256];
__device__ __align__(128) uint2 g_edge  [N_EDGES];              // {src, norm-bits} sorted by dst
__device__ __align__(128) float g_W2p [FDIM * FDIM];
__device__ __align__(128) float g_cvec[FDIM];
__device__ __align__(128) float g_Wcp [FDIM * OUT_DIM];
__device__ __align__(128) float g_bcp [OUT_DIM];
__device__ __align__(128) float g_sum [FDIM];
__device__ __align__(128) float g_sq  [FDIM];

// ---------------- init: deg=1 (self loop), cnt=0 ----------------------------
__global__ void k_init(float* deg, int* cnt) {
    int i = blockIdx.x * blockDim.x + threadIdx.x;
    if (i < N_NODES) { deg[i] = 1.0f; cnt[i] = 0; }
}

__global__ void k_pass1(const float* __restrict__ ewp, const int* __restrict__ col,
                        float* deg, int* cnt) {
    int e = blockIdx.x * blockDim.x + threadIdx.x;
    if (e < N_EDGES) {
        int c = col[e];
        atomicAdd(&deg[c], expf(ewp[e]));
        atomicAdd(&cnt[c], 1);
    }
}

__global__ void k_dinv(const float* __restrict__ deg, float* dinv) {
    int i = blockIdx.x * blockDim.x + threadIdx.x;
    if (i < N_NODES) {
        float d = deg[i];
        dinv[i] = (d > 0.f) ? rsqrtf(d) : 0.f;
    }
}

// ---------------- hierarchical scan (3 kernels, all coalesced) ---------------
__global__ void k_scan1(const int* __restrict__ cnt, int* __restrict__ partial) {
    __shared__ int sh[8];
    int idx = blockIdx.x * 256 + threadIdx.x;
    int v = (idx < N_NODES) ? cnt[idx] : 0;
    #pragma unroll
    for (int off = 16; off; off >>= 1) v += __shfl_down_sync(0xffffffffu, v, off);
    if ((threadIdx.x & 31) == 0) sh[threadIdx.x >> 5] = v;
    __syncthreads();
    if (threadIdx.x == 0) {
        int s = 0;
        #pragma unroll
        for (int w = 0; w < 8; w++) s += sh[w];
        partial[blockIdx.x] = s;
    }
}

__global__ void k_scan2(const int* __restrict__ partial, int* __restrict__ pscan,
                        int* __restrict__ start) {
    __shared__ int sh[256];
    int t = threadIdx.x;
    int v = (t < NBLK_SCAN) ? partial[t] : 0;
    sh[t] = v;
    __syncthreads();
    #pragma unroll
    for (int off = 1; off < 256; off <<= 1) {
        int u = (t >= off) ? sh[t - off] : 0;
        __syncthreads();
        sh[t] += u;
        __syncthreads();
    }
    if (t < NBLK_SCAN) pscan[t] = sh[t] - v;   // exclusive
    if (t == 0) start[N_NODES] = N_EDGES;
}

__global__ void k_scan3(const int* __restrict__ cnt, const int* __restrict__ pscan,
                        int* __restrict__ start, int* __restrict__ cursor) {
    __shared__ int sh[256];
    int t = threadIdx.x;
    int idx = blockIdx.x * 256 + t;
    int v = (idx < N_NODES) ? cnt[idx] : 0;
    sh[t] = v;
    __syncthreads();
    #pragma unroll
    for (int off = 1; off < 256; off <<= 1) {
        int u = (t >= off) ? sh[t - off] : 0;
        __syncthreads();
        sh[t] += u;
        __syncthreads();
    }
    if (idx < N_NODES) {
        int excl = sh[t] - v + pscan[blockIdx.x];
        start[idx] = excl;
        cursor[idx] = excl;
    }
}

// ---------------- bucket scatter: sorted {src, norm} per destination ---------
__global__ void k_sortedges(const float* __restrict__ ewp, const int* __restrict__ row,
                            const int* __restrict__ col, const float* __restrict__ dinv,
                            int* cursor, uint2* __restrict__ edge) {
    int e = blockIdx.x * blockDim.x + threadIdx.x;
    if (e < N_EDGES) {
        int r = row[e];
        int c = col[e];
        float nm = dinv[r] * expf(ewp[e]) * dinv[c];
        int pos = atomicAdd(&cursor[c], 1);
        edge[pos] = make_uint2((unsigned)r, __float_as_uint(nm));
    }
}

// ---------------- tensor-core GEMM core -------------------------------------
// mma.sync.m16n8k16, fp32 accumulate, fp16 output. Block tile 128x128, K=128
// fully smem-resident. 8 warps: warp (wm, wn) computes rows 32*wm, cols 64*wn.
// A16MODE=0: A fp32, row remap ((j&1)*N_NODES + (j>>1)); A16MODE=1: A fp16 identity.
__device__ __forceinline__ uint32_t smem_u32(const void* p) {
    return (uint32_t)__cvta_generic_to_shared(p);
}

template <int A16MODE>
__device__ __forceinline__ void gemm_mma_body(const void* __restrict__ Av,
                                              const float* __restrict__ W,
                                              const float* __restrict__ cvec,
                                              __half* __restrict__ C, int Mrows) {
    extern __shared__ __half smh[];
    __half* sA = smh;                       // [128][SROW]
    __half* sW = smh + 128 * SROW;          // [128][SROW]
    float* scv = (float*)(sW + 128 * SROW); // [128]
    const int tid = threadIdx.x;
    const int wid = tid >> 5, lane = tid & 31;
    const int wm = wid >> 1;                // 0..3
    const int wn = wid & 1;                 // 0..1

    // load W (fp32 -> fp16) + cvec once per block
    for (int i = tid; i < 2048; i += 256) {             // 128 rows x 16 chunks
        int r = i >> 4, c8 = i & 15;
        float4 w0 = __ldg((const float4*)W + r * 32 + c8 * 2);
        float4 w1 = __ldg((const float4*)W + r * 32 + c8 * 2 + 1);
        __half2 h[4];
        h[0] = __floats2half2_rn(w0.x, w0.y);
        h[1] = __floats2half2_rn(w0.z, w0.w);
        h[2] = __floats2half2_rn(w1.x, w1.y);
        h[3] = __floats2half2_rn(w1.z, w1.w);
        *(uint4*)(sW + r * SROW + c8 * 8) = *(uint4*)h;
    }
    if (tid < FDIM) scv[tid] = cvec ? cvec[tid] : 0.f;

    const int ntile = (Mrows + 127) >> 7;
    for (int tile = blockIdx.x; tile < ntile; tile += gridDim.x) {
        const int base = tile << 7;
        __syncthreads();    // previous iter reads done; W/cvec writes ordered (iter 0)
        for (int i = tid; i < 2048; i += 256) {
            int r = i >> 4, c8 = i & 15;
            int grow = base + r;
            uint4 st = make_uint4(0u, 0u, 0u, 0u);
            if (grow < Mrows) {
                if (A16MODE) {
                    const __half* A16 = (const __half*)Av;
                    st = __ldg((const uint4*)(A16 + (size_t)grow * FDIM) + c8);
                } else {
                    const float* A = (const float*)Av;
                    int irow = (grow & 1) * N_NODES + (grow >> 1);
                    float4 a0 = __ldg((const float4*)A + (size_t)irow * 32 + c8 * 2);
                    float4 a1 = __ldg((const float4*)A + (size_t)irow * 32 + c8 * 2 + 1);
                    __half2 h[4];
                    h[0] = __floats2half2_rn(a0.x, a0.y);
                    h[1] = __floats2half2_rn(a0.z, a0.w);
                    h[2] = __floats2half2_rn(a1.x, a1.y);
                    h[3] = __floats2half2_rn(a1.z, a1.w);
                    st = *(uint4*)h;
                }
            }
            *(uint4*)(sA + r * SROW + c8 * 8) = st;
        }
        __syncthreads();

        float acc[2][8][4];
        #pragma unroll
        for (int mt = 0; mt < 2; mt++)
            #pragma unroll
            for (int nt = 0; nt < 8; nt++)
                #pragma unroll
                for (int k = 0; k < 4; k++) acc[mt][nt][k] = 0.f;

        #pragma unroll
        for (int ks = 0; ks < 8; ks++) {
            const int k0 = ks * 16;
            uint32_t a[2][4];
            #pragma unroll
            for (int mt = 0; mt < 2; mt++) {
                int r = wm * 32 + mt * 16 + (lane & 15);
                int kk = k0 + ((lane & 16) ? 8 : 0);
                uint32_t addr = smem_u32(sA + r * SROW + kk);
                asm volatile("ldmatrix.sync.aligned.m8n8.x4.shared.b16 {%0,%1,%2,%3}, [%4];"
                             : "=r"(a[mt][0]), "=r"(a[mt][1]), "=r"(a[mt][2]), "=r"(a[mt][3])
                             : "r"(addr));
            }
            uint32_t b[8][2];
            #pragma unroll
            for (int np = 0; np < 4; np++) {
                int r = k0 + (lane & 15);
                int cc = wn * 64 + np * 16 + ((lane & 16) ? 8 : 0);
                uint32_t addr = smem_u32(sW + r * SROW + cc);
                uint32_t r0, r1, r2, r3;
                asm volatile("ldmatrix.sync.aligned.m8n8.x4.trans.shared.b16 {%0,%1,%2,%3}, [%4];"
                             : "=r"(r0), "=r"(r1), "=r"(r2), "=r"(r3)
                             : "r"(addr));
                b[np * 2][0] = r0;     b[np * 2][1] = r1;
                b[np * 2 + 1][0] = r2; b[np * 2 + 1][1] = r3;
            }
            #pragma unroll
            for (int mt = 0; mt < 2; mt++)
                #pragma unroll
                for (int nt = 0; nt < 8; nt++)
                    asm volatile("mma.sync.aligned.m16n8k16.row.col.f32.f16.f16.f32 "
                                 "{%0,%1,%2,%3}, {%4,%5,%6,%7}, {%8,%9}, {%0,%1,%2,%3};"
                                 : "+f"(acc[mt][nt][0]), "+f"(acc[mt][nt][1]),
                                   "+f"(acc[mt][nt][2]), "+f"(acc[mt][nt][3])
                                 : "r"(a[mt][0]), "r"(a[mt][1]), "r"(a[mt][2]), "r"(a[mt][3]),
                                   "r"(b[nt][0]), "r"(b[nt][1]));
        }

        #pragma unroll
        for (int mt = 0; mt < 2; mt++) {
            int r0 = base + wm * 32 + mt * 16 + (lane >> 2);
            int r1 = r0 + 8;
            #pragma unroll
            for (int nt = 0; nt < 8; nt++) {
                int cc = wn * 64 + nt * 8 + (lane & 3) * 2;
                float cv0 = scv[cc], cv1 = scv[cc + 1];
                if (r0 < Mrows) {
                    __half2 h = __floats2half2_rn(acc[mt][nt][0] + cv0, acc[mt][nt][1] + cv1);
                    *(__half2*)(C + (size_t)r0 * FDIM + cc) = h;
                }
                if (r1 < Mrows) {
                    __half2 h = __floats2half2_rn(acc[mt][nt][2] + cv0, acc[mt][nt][3] + cv1);
                    *(__half2*)(C + (size_t)r1 * FDIM + cc) = h;
                }
            }
        }
    }
}

__global__ __launch_bounds__(256) void k_gemm_mma_f32(const float* __restrict__ A,
                                                      const float* __restrict__ W,
                                                      const float* __restrict__ cvec,
                                                      __half* __restrict__ C, int Mrows) {
    gemm_mma_body<0>(A, W, cvec, C, Mrows);
}

__global__ __launch_bounds__(256) void k_gemm_mma_f16(const __half* __restrict__ A,
                                                      const float* __restrict__ W,
                                                      const float* __restrict__ cvec,
                                                      __half* __restrict__ C, int Mrows) {
    gemm_mma_body<1>(A, W, cvec, C, Mrows);
}

// ---------------- fused aggregate (BOTH batches) + self + bias + relu + BN ---
__device__ __forceinline__ void h8f(uint4 u, float4& A, float4& B) {
    float2 f0 = __half22float2(*(__half2*)&u.x);
    float2 f1 = __half22float2(*(__half2*)&u.y);
    float2 f2 = __half22float2(*(__half2*)&u.z);
    float2 f3 = __half22float2(*(__half2*)&u.w);
    A = make_float4(f0.x, f0.y, f1.x, f1.y);
    B = make_float4(f2.x, f2.y, f3.x, f3.y);
}

// OUT16=1: write fp16 interleaved t (for layer-2 GEMM); OUT16=0: write fp32 t.
template <int OUT16>
__device__ __forceinline__ void agg_body(const __half* __restrict__ xwi,
                                         const uint2* __restrict__ edge,
                                         const int* __restrict__ start,
                                         const float* __restrict__ dinv,
                                         const float* __restrict__ bias,
                                         void* __restrict__ tout,
                                         float* __restrict__ gsum,
                                         float* __restrict__ gsq) {
    const int tid = threadIdx.x;
    const int lane = tid & 31;
    const int fg = lane & 15;          // feature group: features 8*fg .. 8*fg+7
    const int gw = (blockIdx.x * blockDim.x + tid) >> 5;
    const int nwarps = (gridDim.x * blockDim.x) >> 5;
    const float4 bv0 = ((const float4*)bias)[fg * 2];
    const float4 bv1 = ((const float4*)bias)[fg * 2 + 1];
    float s[8] = {0.f, 0.f, 0.f, 0.f, 0.f, 0.f, 0.f, 0.f};
    float q[8] = {0.f, 0.f, 0.f, 0.f, 0.f, 0.f, 0.f, 0.f};

    for (int n = gw; n < N_NODES; n += nwarps) {
        const int st = start[n];
        const int en = start[n + 1];
        const float d = dinv[n];
        const float d2 = d * d;
        const uint4* blk = (const uint4*)(xwi + (size_t)(2 * n) * FDIM);
        float4 sv0, sv1;
        h8f(__ldg(blk + lane), sv0, sv1);
        float4 acc0 = make_float4(d2 * sv0.x, d2 * sv0.y, d2 * sv0.z, d2 * sv0.w);
        float4 acc1 = make_float4(d2 * sv1.x, d2 * sv1.y, d2 * sv1.z, d2 * sv1.w);

        const int cnt4 = (en - st) >> 2;
        int e = st;
        if (cnt4 > 0) {
            uint2 m0 = __ldg(&edge[e]);
            uint2 m1 = __ldg(&edge[e + 1]);
            uint2 m2 = __ldg(&edge[e + 2]);
            uint2 m3 = __ldg(&edge[e + 3]);
            for (int g = 0; g < cnt4; g++) {
                uint2 p0, p1, p2, p3;
                const int ne = e + 4;
                if (g + 1 < cnt4) {
                    p0 = __ldg(&edge[ne]);
                    p1 = __ldg(&edge[ne + 1]);
                    p2 = __ldg(&edge[ne + 2]);
                    p3 = __ldg(&edge[ne + 3]);
                }
                uint4 e0 = __ldg((const uint4*)(xwi + (size_t)(2 * m0.x) * FDIM) + lane);
                uint4 e1 = __ldg((const uint4*)(xwi + (size_t)(2 * m1.x) * FDIM) + lane);
                uint4 e2 = __ldg((const uint4*)(xwi + (size_t)(2 * m2.x) * FDIM) + lane);
                uint4 e3 = __ldg((const uint4*)(xwi + (size_t)(2 * m3.x) * FDIM) + lane);
                float w0 = __uint_as_float(m0.y), w1 = __uint_as_float(m1.y);
                float w2 = __uint_as_float(m2.y), w3 = __uint_as_float(m3.y);
                float4 aA, aB;
                h8f(e0, aA, aB);
                acc0.x = fmaf(w0, aA.x, acc0.x); acc0.y = fmaf(w0, aA.y, acc0.y);
                acc0.z = fmaf(w0, aA.z, acc0.z); acc0.w = fmaf(w0, aA.w, acc0.w);
                acc1.x = fmaf(w0, aB.x, acc1.x); acc1.y = fmaf(w0, aB.y, acc1.y);
                acc1.z = fmaf(w0, aB.z, acc1.z); acc1.w = fmaf(w0, aB.w, acc1.w);
                h8f(e1, aA, aB);
                acc0.x = fmaf(w1, aA.x, acc0.x); acc0.y = fmaf(w1, aA.y, acc0.y);
                acc0.z = fmaf(w1, aA.z, acc0.z); acc0.w = fmaf(w1, aA.w, acc0.w);
                acc1.x = fmaf(w1, aB.x, acc1.x); acc1.y = fmaf(w1, aB.y, acc1.y);
                acc1.z = fmaf(w1, aB.z, acc1.z); acc1.w = fmaf(w1, aB.w, acc1.w);
                h8f(e2, aA, aB);
                acc0.x = fmaf(w2, aA.x, acc0.x); acc0.y = fmaf(w2, aA.y, acc0.y);
                acc0.z = fmaf(w2, aA.z, acc0.z); acc0.w = fmaf(w2, aA.w, acc0.w);
                acc1.x = fmaf(w2, aB.x, acc1.x); acc1.y = fmaf(w2, aB.y, acc1.y);
                acc1.z = fmaf(w2, aB.z, acc1.z); acc1.w = fmaf(w2, aB.w, acc1.w);
                h8f(e3, aA, aB);
                acc0.x = fmaf(w3, aA.x, acc0.x); acc0.y = fmaf(w3, aA.y, acc0.y);
                acc0.z = fmaf(w3, aA.z, acc0.z); acc0.w = fmaf(w3, aA.w, acc0.w);
                acc1.x = fmaf(w3, aB.x, acc1.x); acc1.y = fmaf(w3, aB.y, acc1.y);
                acc1.z = fmaf(w3, aB.z, acc1.z); acc1.w = fmaf(w3, aB.w, acc1.w);
                m0 = p0; m1 = p1; m2 = p2; m3 = p3;
                e = ne;
            }
        }
        for (; e < en; e++) {
            uint2 m = __ldg(&edge[e]);
            uint4 ev = __ldg((const uint4*)(xwi + (size_t)(2 * m.x) * FDIM) + lane);
            float w = __uint_as_float(m.y);
            float4 aA, aB;
            h8f(ev, aA, aB);
            acc0.x = fmaf(w, aA.x, acc0.x); acc0.y = fmaf(w, aA.y, acc0.y);
            acc0.z = fmaf(w, aA.z, acc0.z); acc0.w = fmaf(w, aA.w, acc0.w);
            acc1.x = fmaf(w, aB.x, acc1.x); acc1.y = fmaf(w, aB.y, acc1.y);
            acc1.z = fmaf(w, aB.z, acc1.z); acc1.w = fmaf(w, aB.w, acc1.w);
        }

        float4 o0, o1;
        o0.x = fmaxf(acc0.x + bv0.x, 0.f);
        o0.y = fmaxf(acc0.y + bv0.y, 0.f);
        o0.z = fmaxf(acc0.z + bv0.z, 0.f);
        o0.w = fmaxf(acc0.w + bv0.w, 0.f);
        o1.x = fmaxf(acc1.x + bv1.x, 0.f);
        o1.y = fmaxf(acc1.y + bv1.y, 0.f);
        o1.z = fmaxf(acc1.z + bv1.z, 0.f);
        o1.w = fmaxf(acc1.w + bv1.w, 0.f);
        if (OUT16) {
            __half2 hp[4];
            hp[0] = __floats2half2_rn(o0.x, o0.y);
            hp[1] = __floats2half2_rn(o0.z, o0.w);
            hp[2] = __floats2half2_rn(o1.x, o1.y);
            hp[3] = __floats2half2_rn(o1.z, o1.w);
            ((uint4*)((__half*)tout + (size_t)(2 * n) * FDIM))[lane] = *(uint4*)hp;
        } else {
            float4* dst = (float4*)((float*)tout + (size_t)(2 * n) * FDIM);
            dst[lane * 2] = o0;
            dst[lane * 2 + 1] = o1;
        }
        s[0] += o0.x; q[0] += o0.x * o0.x;
        s[1] += o0.y; q[1] += o0.y * o0.y;
        s[2] += o0.z; q[2] += o0.z * o0.z;
        s[3] += o0.w; q[3] += o0.w * o0.w;
        s[4] += o1.x; q[4] += o1.x * o1.x;
        s[5] += o1.y; q[5] += o1.y * o1.y;
        s[6] += o1.z; q[6] += o1.z * o1.z;
        s[7] += o1.w; q[7] += o1.w * o1.w;
    }

    __shared__ float sh[256 * 16];
    #pragma unroll
    for (int j = 0; j < 8; j++) { sh[tid * 16 + j] = s[j]; sh[tid * 16 + 8 + j] = q[j]; }
    __syncthreads();
    if (tid < FDIM) {
        const int fgr = tid >> 3;
        const int j = tid & 7;
        float as = 0.f, aq = 0.f;
        #pragma unroll
        for (int k = 0; k < 16; k++) {
            int src = (k * 16 + fgr) * 16;
            as += sh[src + j];
            aq += sh[src + 8 + j];
        }
        atomicAdd(&gsum[tid], as);
        atomicAdd(&gsq[tid], aq);
    }
}

__global__ __launch_bounds__(256) void k_agg_h(const __half* __restrict__ xwi,
                                               const uint2* __restrict__ edge,
                                               const int* __restrict__ start,
                                               const float* __restrict__ dinv,
                                               const float* __restrict__ bias,
                                               __half* __restrict__ t16,
                                               float* __restrict__ gsum,
                                               float* __restrict__ gsq) {
    agg_body<1>(xwi, edge, start, dinv, bias, t16, gsum, gsq);
}

__global__ __launch_bounds__(256) void k_agg_f(const __half* __restrict__ xwi,
                                               const uint2* __restrict__ edge,
                                               const int* __restrict__ start,
                                               const float* __restrict__ dinv,
                                               const float* __restrict__ bias,
                                               float* __restrict__ tf,
                                               float* __restrict__ gsum,
                                               float* __restrict__ gsq) {
    agg_body<0>(xwi, edge, start, dinv, bias, tf, gsum, gsq);
}

// ---------------- fold BN into next weight matrix ----------------------------
__global__ void k_fold(const float* __restrict__ gsum, const float* __restrict__ gsq,
                       const float* __restrict__ gamma, const float* __restrict__ beta,
                       const float* __restrict__ Wsrc, int J,
                       const float* __restrict__ extra_bias,
                       float* __restrict__ Wp, float* __restrict__ cv) {
    __shared__ float ssc[FDIM], ssh[FDIM];
    int t = threadIdx.x;  // 128
    float mu = gsum[t] * (1.0f / M_ROWS);
    float var = gsq[t] * (1.0f / M_ROWS) - mu * mu;
    float sc = gamma[t] * rsqrtf(var + EPSBN);
    ssc[t] = sc;
    ssh[t] = beta[t] - mu * sc;
    __syncthreads();
    if (t < J) {
        float acc = extra_bias ? extra_bias[t] : 0.f;
        for (int k = 0; k < FDIM; k++) {
            float w = Wsrc[k * J + t];
            Wp[k * J + t] = ssc[k] * w;
            acc += ssh[k] * w;
        }
        cv[t] = acc;
    }
}

// ---------------- classifier: out = t2 @ Wcp + bcp (un-interleaves) ----------
__global__ void k_classifier(const float* __restrict__ t2, const float* __restrict__ Wcp,
                             const float* __restrict__ bcp, float* __restrict__ out) {
    __shared__ float sWT[OUT_DIM * FDIM];  // [o][k]
    __shared__ float sb[OUT_DIM];
    int tid = threadIdx.x;  // 256
    for (int i = tid; i < FDIM * OUT_DIM; i += 256) {
        int k = i / OUT_DIM, o = i % OUT_DIM;
        sWT[o * FDIM + k] = Wcp[i];
    }
    if (tid < OUT_DIM) sb[tid] = bcp[tid];
    __syncthreads();

    int gt = blockIdx.x * blockDim.x + tid;
    int warp = gt >> 5;
    int lane = gt & 31;
    int nw = (gridDim.x * blockDim.x) >> 5;
    for (int rowJ = warp; rowJ < M_ROWS; rowJ += nw) {
        float4 v = __ldg((const float4*)(t2 + (size_t)rowJ * FDIM) + lane);
        float y[OUT_DIM];
        #pragma unroll
        for (int o = 0; o < OUT_DIM; o++) {
            float4 w = ((const float4*)(sWT + o * FDIM))[lane];
            y[o] = v.x * w.x + v.y * w.y + v.z * w.z + v.w * w.w;
        }
        #pragma unroll
        for (int off = 16; off; off >>= 1)
            #pragma unroll
            for (int o = 0; o < OUT_DIM; o++)
                y[o] += __shfl_xor_sync(0xffffffffu, y[o], off);
        if (lane < OUT_DIM) {
            int n = rowJ >> 1, b = rowJ & 1;
            out[(size_t)(b * N_NODES + n) * OUT_DIM + lane] = y[lane] + sb[lane];
        }
    }
}

// ---------------- launch -----------------------------------------------------
extern "C" void kernel_launch(void* const* d_in, const int* in_sizes, int n_in,
                              void* d_out, int out_size) {
    const float* x   = (const float*)d_in[0];
    const int*   ei  = (const int*)d_in[1];
    const float* ewp = (const float*)d_in[2];
    const float* W1  = (const float*)d_in[3];
    const float* b1  = (const float*)d_in[4];
    const float* W2  = (const float*)d_in[5];
    const float* b2  = (const float*)d_in[6];
    const float* g1  = (const float*)d_in[7];
    const float* be1 = (const float*)d_in[8];
    const float* g2  = (const float*)d_in[9];
    const float* be2 = (const float*)d_in[10];
    const float* Wc  = (const float*)d_in[11];
    const float* bc  = (const float*)d_in[12];
    float* out = (float*)d_out;
    const int* row = ei;
    const int* col = ei + N_EDGES;

    float *p_t, *p_dinv, *p_deg;
    float *p_W2p, *p_cvec, *p_Wcp, *p_bcp, *p_sum, *p_sq;
    int *p_cnt, *p_start, *p_cursor, *p_partial, *p_pscan;
    uint2* p_edge;
    __half *p_xw, *p_t16;
    cudaGetSymbolAddress((void**)&p_xw,   g_xw);
    cudaGetSymbolAddress((void**)&p_t16,  g_t16);
    cudaGetSymbolAddress((void**)&p_t,    g_t);
    cudaGetSymbolAddress((void**)&p_dinv, g_dinv);
    cudaGetSymbolAddress((void**)&p_deg,  g_deg);
    cudaGetSymbolAddress((void**)&p_cnt,  g_cnt);
    cudaGetSymbolAddress((void**)&p_start, g_start);
    cudaGetSymbolAddress((void**)&p_cursor, g_cursor);
    cudaGetSymbolAddress((void**)&p_partial, g_partial);
    cudaGetSymbolAddress((void**)&p_pscan, g_pscan);
    cudaGetSymbolAddress((void**)&p_edge, g_edge);
    cudaGetSymbolAddress((void**)&p_W2p,  g_W2p);
    cudaGetSymbolAddress((void**)&p_cvec, g_cvec);
    cudaGetSymbolAddress((void**)&p_Wcp,  g_Wcp);
    cudaGetSymbolAddress((void**)&p_bcp,  g_bcp);
    cudaGetSymbolAddress((void**)&p_sum,  g_sum);
    cudaGetSymbolAddress((void**)&p_sq,   g_sq);

    const int SMEM_MMA = 2 * 128 * SROW * 2 + FDIM * 4;   // ~70.2 KB
    (void)cudaFuncSetAttribute(k_gemm_mma_f32, cudaFuncAttributeMaxDynamicSharedMemorySize, SMEM_MMA);
    (void)cudaFuncSetAttribute(k_gemm_mma_f16, cudaFuncAttributeMaxDynamicSharedMemorySize, SMEM_MMA);

    // --- CSR build + layer-1 GEMM (gemm placed at launch #4 for ncu) ---
    k_init      <<<(N_NODES + 255) / 256, 256>>>(p_deg, p_cnt);                        // 1
    k_pass1     <<<(N_EDGES + 255) / 256, 256>>>(ewp, col, p_deg, p_cnt);              // 2
    k_dinv      <<<(N_NODES + 255) / 256, 256>>>(p_deg, p_dinv);                       // 3
    k_gemm_mma_f32<<<782, 256, SMEM_MMA>>>(x, W1, nullptr, p_xw, M_ROWS);              // 4 <- ncu
    k_scan1     <<<NBLK_SCAN, 256>>>(p_cnt, p_partial);
    k_scan2     <<<1, 256>>>(p_partial, p_pscan, p_start);
    k_scan3     <<<NBLK_SCAN, 256>>>(p_cnt, p_pscan, p_start, p_cursor);
    k_sortedges <<<(N_EDGES + 255) / 256, 256>>>(ewp, row, col, p_dinv, p_cursor, p_edge);

    // --- layer 1 aggregation (both batches; writes fp16 t16) ---
    cudaMemsetAsync(p_sum, 0, FDIM * sizeof(float), 0);
    cudaMemsetAsync(p_sq,  0, FDIM * sizeof(float), 0);
    k_agg_h<<<1184, 256>>>(p_xw, p_edge, p_start, p_dinv, b1, p_t16, p_sum, p_sq);
    k_fold<<<1, 128>>>(p_sum, p_sq, g1, be1, W2, FDIM, nullptr, p_W2p, p_cvec);

    // --- layer 2 (BN1 folded into W2; t16 fp16 -> raw-copy A path) ---
    k_gemm_mma_f16<<<782, 256, SMEM_MMA>>>(p_t16, p_W2p, p_cvec, p_xw, M_ROWS);
    cudaMemsetAsync(p_sum, 0, FDIM * sizeof(float), 0);
    cudaMemsetAsync(p_sq,  0, FDIM * sizeof(float), 0);
    k_agg_f<<<1184, 256>>>(p_xw, p_edge, p_start, p_dinv, b2, p_t, p_sum, p_sq);
    k_fold<<<1, 128>>>(p_sum, p_sq, g2, be2, Wc, OUT_DIM, bc, p_Wcp, p_bcp);

    // --- classifier (BN2 folded into Wc; fp32 t -> no extra rounding) ---
    k_classifier<<<1024, 256>>>(p_t, p_Wcp, p_bcp, out);
}